// round 9
// baseline (speedup 1.0000x reference)
#include <cuda_runtime.h>
#include <math.h>

#define B_DIM 4096
#define N_DIM 512
#define H_DIM 1024
#define NOPS  20
#define PWRK  12               // squarings -> p = 2^12 = 4096
#define PINV  (1.0f/4096.0f)

// ---------------- static device scratch (no allocations allowed) ----------------
static __device__ float g_C[H_DIM * H_DIM];                 // W^T W      (4 MB)
static __device__ float g_Asq[2][N_DIM * N_DIM];            // squaring ping-pong (2 MB)
static __device__ float g_u[(size_t)B_DIM * H_DIM];         // W^T x      (16 MB)
static __device__ float g_zbuf[2][(size_t)B_DIM * H_DIM];   // z ping-pong (32 MB)
static __device__ float g_zpbuf[2][(size_t)B_DIM * H_DIM];  // z_prev ping-pong (32 MB)
static __device__ float g_scal[8];                          // [0]=log accum s, [1]=1/tr, [3]=1/L, [4]=lam
static __device__ float g_w[16 * 24];                       // per-iter: aw[20], bw0, bw1

// ---------------- 20-op activation mixture (matches JAX semantics) ----------------
__device__ __forceinline__ float act_mix(float v, const float* aw, float lam) {
    float av  = fabsf(v);
    float e   = expf(-av);                 // exp(-|v|)
    float i1e = 1.0f / (1.0f + e);
    float sig = (v >= 0.f) ? i1e : e * i1e;            // sigmoid(v)
    float sp  = fmaxf(v, 0.f) + log1pf(e);             // softplus(v)
    float e2  = e * e;
    float tha = (1.f - e2) / (1.f + e2);               // tanh(|v|)
    float th  = (v >= 0.f) ? tha : -tha;               // tanh(v)
    float oms = 1.f - sig;                              // sigmoid(-v) = exp(-softplus(v))
    float q   = oms * oms;                              // exp(-2*softplus(v))
    float msh = (1.f - q) / (1.f + q);                  // tanh(softplus(v))
    float erv = erff(v * 0.70710678118654752f);
    float em1 = e - 1.f;                                // expm1(v) for v<0
    float elu = (v > 0.f) ? v : em1;
    float r6  = fminf(fmaxf(v + 3.f, 0.f), 6.f) * (1.f / 6.f);

    float r;
    r  = aw[0]  * ((v > lam) ? (v - lam) : ((v < -lam) ? (v + lam) : 0.f)); // softshrink
    r += aw[1]  * fmaxf(v, 0.f);                                           // relu
    r += aw[2]  * v;                                                       // identity
    r += aw[3]  * (0.5f * v * (1.f + erv));                                // gelu (exact)
    r += aw[4]  * elu;                                                     // elu
    r += aw[5]  * ((av > lam) ? v : 0.f);                                  // hardshrink
    r += aw[6]  * fminf(fmaxf(v, -1.f), 1.f);                              // hardtanh
    r += aw[7]  * (v * r6);                                                // hardswish
    r += aw[8]  * (1.0507009873554805f * ((v > 0.f) ? v : 1.6732632423543772f * em1)); // selu
    r += aw[9]  * elu;                                                     // celu(alpha=1)
    r += aw[10] * ((v >= 0.f) ? v : 0.01f * v);                            // leaky_relu
    r += aw[11] * (v - sp);                                                // log_sigmoid
    r += aw[12] * (v - th);                                                // tanhshrink
    r += aw[13] * (v / (1.f + av));                                        // softsign
    r += aw[14] * sp;                                                      // softplus
    r += aw[15] * th;                                                      // tanh
    r += aw[16] * sig;                                                     // sigmoid
    r += aw[17] * r6;                                                      // hardsigmoid
    r += aw[18] * (v * sig);                                               // silu
    r += aw[19] * (v * msh);                                               // mish
    return r;
}

// ---------------- GEMM building blocks: 128x128 tile, BK=16, 256 thr, 8x8/thr ----------------
// load [128m x 16k] from row-major [m][k] (stride ld) -> transposed s[16][128]
__device__ __forceinline__ void load_A_T(float s[16][128], const float* src,
                                         int m0, int k0, int ld, int t) {
#pragma unroll
    for (int l = 0; l < 2; ++l) {
        int fid = t + l * 256;
        int row = fid >> 2;
        int cv  = (fid & 3) * 4;
        float4 v = *(const float4*)&src[(size_t)(m0 + row) * ld + k0 + cv];
        s[cv + 0][row] = v.x; s[cv + 1][row] = v.y;
        s[cv + 2][row] = v.z; s[cv + 3][row] = v.w;
    }
}
// load [16k x 128n] direct from row-major [k][n] (stride ld) -> s[16][128]
__device__ __forceinline__ void load_B_N(float s[16][128], const float* src,
                                         int k0, int n0, int ld, int t) {
#pragma unroll
    for (int l = 0; l < 2; ++l) {
        int fid = t + l * 256;
        int row = fid >> 5;
        int cv  = (fid & 31) * 4;
        *(float4*)&s[row][cv] = *(const float4*)&src[(size_t)(k0 + row) * ld + n0 + cv];
    }
}
__device__ __forceinline__ void mma_chunk(const float (*a_s)[128], const float (*b_s)[128],
                                          int tx, int ty, float acc[8][8]) {
#pragma unroll
    for (int kk = 0; kk < 16; ++kk) {
        float ar[8], br[8];
        *(float4*)&ar[0] = *(const float4*)&a_s[kk][ty * 8];
        *(float4*)&ar[4] = *(const float4*)&a_s[kk][ty * 8 + 4];
        *(float4*)&br[0] = *(const float4*)&b_s[kk][tx * 8];
        *(float4*)&br[4] = *(const float4*)&b_s[kk][tx * 8 + 4];
#pragma unroll
        for (int i = 0; i < 8; ++i)
#pragma unroll
            for (int j = 0; j < 8; ++j)
                acc[i][j] = fmaf(ar[i], br[j], acc[i][j]);
    }
}
__device__ __forceinline__ void store_tile(float* outp, int ldo, int m0, int n0,
                                           int tx, int ty, const float acc[8][8], float scale) {
#pragma unroll
    for (int i = 0; i < 8; ++i) {
        float v[8];
#pragma unroll
        for (int j = 0; j < 8; ++j) v[j] = acc[i][j] * scale;
        size_t off = (size_t)(m0 + ty * 8 + i) * ldo + n0 + tx * 8;
        *(float4*)&outp[off]     = *(float4*)&v[0];
        *(float4*)&outp[off + 4] = *(float4*)&v[4];
    }
}

// ---------------- one-time kernels ----------------
// A = W W^T  [512x512], K=1024
__global__ __launch_bounds__(256) void k_gemm_wwT(const float* __restrict__ W) {
    __shared__ float a_s[16][128], b_s[16][128];
    int t = threadIdx.x, tx = t & 15, ty = t >> 4;
    int n0 = blockIdx.x * 128, m0 = blockIdx.y * 128;
    float acc[8][8] = {};
    for (int k0 = 0; k0 < H_DIM; k0 += 16) {
        load_A_T(a_s, W, m0, k0, H_DIM, t);
        load_A_T(b_s, W, n0, k0, H_DIM, t);
        __syncthreads();
        mma_chunk(a_s, b_s, tx, ty, acc);
        __syncthreads();
    }
    store_tile(g_Asq[0], N_DIM, m0, n0, tx, ty, acc, 1.0f);
}
// C = W^T W  [1024x1024], K=512
__global__ __launch_bounds__(256) void k_gemm_C(const float* __restrict__ W) {
    __shared__ float a_s[16][128], b_s[16][128];
    int t = threadIdx.x, tx = t & 15, ty = t >> 4;
    int n0 = blockIdx.x * 128, m0 = blockIdx.y * 128;
    float acc[8][8] = {};
    for (int k0 = 0; k0 < N_DIM; k0 += 16) {
        load_B_N(a_s, W, k0, m0, H_DIM, t);   // Aop[m,k] = W[k,m]
        load_B_N(b_s, W, k0, n0, H_DIM, t);
        __syncthreads();
        mma_chunk(a_s, b_s, tx, ty, acc);
        __syncthreads();
    }
    store_tile(g_C, H_DIM, m0, n0, tx, ty, acc, 1.0f);
}
// u = x * W  [4096x1024], K=512
__global__ __launch_bounds__(256) void k_gemm_u(const float* __restrict__ x,
                                                const float* __restrict__ W) {
    __shared__ float a_s[16][128], b_s[16][128];
    int t = threadIdx.x, tx = t & 15, ty = t >> 4;
    int n0 = blockIdx.x * 128, m0 = blockIdx.y * 128;
    float acc[8][8] = {};
    for (int k0 = 0; k0 < N_DIM; k0 += 16) {
        load_A_T(a_s, x, m0, k0, N_DIM, t);
        load_B_N(b_s, W, k0, n0, H_DIM, t);
        __syncthreads();
        mma_chunk(a_s, b_s, tx, ty, acc);
        __syncthreads();
    }
    store_tile(g_u, H_DIM, m0, n0, tx, ty, acc, 1.0f);
}
// trace of g_Asq[sel]; update log accumulator; final -> L, 1/L, lam
__global__ void k_trace(int sel, int first, int last) {
    __shared__ float red[512];
    int t = threadIdx.x;
    red[t] = g_Asq[sel][t * N_DIM + t];
    __syncthreads();
    for (int s = 256; s > 0; s >>= 1) { if (t < s) red[t] += red[t + s]; __syncthreads(); }
    if (t == 0) {
        float tr = red[0];
        float s0 = first ? 0.f : g_scal[0];
        if (!last) {
            g_scal[0] = 2.f * (s0 + logf(tr));
            g_scal[1] = 1.f / tr;
        } else {
            float lnl = (s0 + logf(tr)) * PINV;
            float L = expf(lnl);
            g_scal[2] = L;
            g_scal[3] = 1.f / L;
            g_scal[4] = 0.001f / L;
        }
    }
}
// g_Asq[src^1] = (g_Asq[src]/tr)^2
__global__ __launch_bounds__(256) void k_gemm_square(int src) {
    __shared__ float a_s[16][128], b_s[16][128];
    int t = threadIdx.x, tx = t & 15, ty = t >> 4;
    int n0 = blockIdx.x * 128, m0 = blockIdx.y * 128;
    const float* in = g_Asq[src];
    float inv = g_scal[1];
    float acc[8][8] = {};
    for (int k0 = 0; k0 < N_DIM; k0 += 16) {
        load_A_T(a_s, in, m0, k0, N_DIM, t);
        load_B_N(b_s, in, k0, n0, N_DIM, t);
        __syncthreads();
        mma_chunk(a_s, b_s, tx, ty, acc);
        __syncthreads();
    }
    store_tile(g_Asq[src ^ 1], N_DIM, m0, n0, tx, ty, acc, inv * inv);
}
// softmax weights per iteration
__global__ void k_weights(const float* __restrict__ alpha, const float* __restrict__ beta, int T) {
    int i = threadIdx.x;
    if (i >= T) return;
    float m = -1e30f;
    for (int k = 0; k < NOPS; ++k) m = fmaxf(m, alpha[i * NOPS + k]);
    float e[NOPS], s = 0.f;
    for (int k = 0; k < NOPS; ++k) { e[k] = expf(alpha[i * NOPS + k] - m); s += e[k]; }
    float invs = 1.f / s;
    for (int k = 0; k < NOPS; ++k) g_w[i * 24 + k] = e[k] * invs;
    float b0 = beta[i * 2], b1 = beta[i * 2 + 1];
    float mb = fmaxf(b0, b1);
    float e0 = expf(b0 - mb), e1 = expf(b1 - mb);
    float ib = 1.f / (e0 + e1);
    g_w[i * 24 + 20] = e0 * ib;
    g_w[i * 24 + 21] = e1 * ib;
}
// iteration 0: z = zprev = 0 -> z_g = u/L, pure elementwise
__global__ void k_iter0(float* zext) {
    __shared__ float smw[24];
    int t = threadIdx.x;
    if (t < 22) smw[t] = g_w[t];
    __syncthreads();
    float invL = g_scal[3], lam = g_scal[4];
    float bw1 = smw[21];
    float* zo  = zext ? zext : g_zbuf[0];
    float* zpo = g_zpbuf[0];
    size_t idx = ((size_t)blockIdx.x * 256 + t) * 4;
    float4 uu = *(const float4*)&g_u[idx];
    float z0 = act_mix(uu.x * invL, smw, lam);
    float z1 = act_mix(uu.y * invL, smw, lam);
    float z2 = act_mix(uu.z * invL, smw, lam);
    float z3 = act_mix(uu.w * invL, smw, lam);
    float4 zv  = make_float4(z0, z1, z2, z3);
    float4 zpv = make_float4(bw1 * z0, bw1 * z1, bw1 * z2, bw1 * z3);
    *(float4*)&zo[idx]  = zv;
    *(float4*)&zpo[idx] = zpv;
}
// fused iteration: Cz GEMM + momentum + gradient step + 20-op mixture + beta mix
__global__ __launch_bounds__(256) void k_gemm_iter(int inSel, int outSel, float* zext,
                                                   int iter, float mom, int write_zp) {
    __shared__ float a_s[16][128], b_s[16][128];
    __shared__ float smw[24];
    int t = threadIdx.x, tx = t & 15, ty = t >> 4;
    if (t < 22) smw[t] = g_w[iter * 24 + t];
    const float* z_in  = g_zbuf[inSel];
    const float* zp_in = g_zpbuf[inSel];
    float* z_out  = zext ? zext : g_zbuf[outSel];
    float* zp_out = g_zpbuf[outSel];
    int n0 = blockIdx.x * 128, m0 = blockIdx.y * 128;
    float acc[8][8] = {};
    for (int k0 = 0; k0 < H_DIM; k0 += 16) {
#pragma unroll
        for (int l = 0; l < 2; ++l) {               // fused z_aux A-tile
            int fid = t + l * 256;
            int row = fid >> 2;
            int cv  = (fid & 3) * 4;
            size_t off = (size_t)(m0 + row) * H_DIM + k0 + cv;
            float4 a = *(const float4*)&z_in[off];
            float4 b = *(const float4*)&zp_in[off];
            a_s[cv + 0][row] = a.x + mom * (a.x - b.x);
            a_s[cv + 1][row] = a.y + mom * (a.y - b.y);
            a_s[cv + 2][row] = a.z + mom * (a.z - b.z);
            a_s[cv + 3][row] = a.w + mom * (a.w - b.w);
        }
        load_B_N(b_s, g_C, k0, n0, H_DIM, t);
        __syncthreads();
        mma_chunk(a_s, b_s, tx, ty, acc);
        __syncthreads();
    }
    float invL = g_scal[3], lam = g_scal[4];
    float bw0 = smw[20], bw1 = smw[21];
#pragma unroll
    for (int i = 0; i < 8; ++i) {
        size_t off = (size_t)(m0 + ty * 8 + i) * H_DIM + n0 + tx * 8;
        float zl[8], zpl[8], ul[8], zo[8], zp2[8];
        *(float4*)&zl[0]  = *(const float4*)&z_in[off];
        *(float4*)&zl[4]  = *(const float4*)&z_in[off + 4];
        *(float4*)&zpl[0] = *(const float4*)&zp_in[off];
        *(float4*)&zpl[4] = *(const float4*)&zp_in[off + 4];
        *(float4*)&ul[0]  = *(const float4*)&g_u[off];
        *(float4*)&ul[4]  = *(const float4*)&g_u[off + 4];
#pragma unroll
        for (int j = 0; j < 8; ++j) {
            float zaux = zl[j] + mom * (zl[j] - zpl[j]);
            float zg   = zaux - (acc[i][j] - ul[j]) * invL;
            float zop  = act_mix(zg, smw, lam);
            zo[j]  = zop;
            zp2[j] = bw0 * zl[j] + bw1 * zop;
        }
        *(float4*)&z_out[off]     = *(float4*)&zo[0];
        *(float4*)&z_out[off + 4] = *(float4*)&zo[4];
        if (write_zp) {
            *(float4*)&zp_out[off]     = *(float4*)&zp2[0];
            *(float4*)&zp_out[off + 4] = *(float4*)&zp2[4];
        }
    }
}

// ---------------- host orchestration (graph-capturable: kernel launches only) ----------------
extern "C" void kernel_launch(void* const* d_in, const int* in_sizes, int n_in,
                              void* d_out, int out_size) {
    const float* x     = (const float*)d_in[0];
    const float* W     = (const float*)d_in[1];
    const float* alpha = (const float*)d_in[2];
    const float* lbeta = (const float*)d_in[3];
    float* out = (float*)d_out;
    int T = in_sizes[2] / NOPS;
    if (T < 1) T = 1;
    if (T > 16) T = 16;

    dim3 thr(256);

    // Spectral norm: A = WW^T, then 12 trace-normalized squarings -> L
    k_gemm_wwT<<<dim3(4, 4), thr>>>(W);
    int cur = 0;
    for (int j = 0; j < PWRK; ++j) {
        k_trace<<<1, 512>>>(cur, (j == 0) ? 1 : 0, 0);
        k_gemm_square<<<dim3(4, 4), thr>>>(cur);
        cur ^= 1;
    }
    k_trace<<<1, 512>>>(cur, 0, 1);

    // One-time precomputes
    k_gemm_C<<<dim3(8, 8), thr>>>(W);
    k_gemm_u<<<dim3(8, 32), thr>>>(x, W);
    k_weights<<<1, 32>>>(alpha, lbeta, T);

    // Iteration 0 (z = zprev = 0): elementwise only
    k_iter0<<<(B_DIM * H_DIM) / (256 * 4), 256>>>((T == 1) ? out : nullptr);

    // Iterations 1..T-1: fused GEMM + epilogue, ping-pong buffers; last writes d_out
    for (int i = 1; i < T; ++i) {
        float mom = (float)((double)i / (double)(i + 3));
        int inSel  = (i + 1) & 1;
        int outSel = i & 1;
        int last = (i == T - 1);
        k_gemm_iter<<<dim3(8, 32), thr>>>(inSel, outSel, last ? out : nullptr,
                                          i, mom, last ? 0 : 1);
    }
}

// round 11
// speedup vs baseline: 1.6026x; 1.6026x over previous
#include <cuda_runtime.h>
#include <cuda_bf16.h>
#include <math.h>
#include <stdint.h>

#define B_DIM 4096
#define N_DIM 512
#define H_DIM 1024
#define NOPS  20
#define PWRK  12               // squarings -> p = 2^12 = 4096
#define PINV  (1.0f/4096.0f)
#define KC    64               // K chunk (bf16 cols) per SMEM stage
#define NCH   (H_DIM / KC)     // 16 chunks

// ---------------- static device scratch (no allocations allowed) ----------------
static __device__ float g_C[H_DIM * H_DIM];                                   // W^T W fp32
static __device__ __align__(16) __nv_bfloat16 g_Chi[H_DIM * H_DIM];           // C hi
static __device__ __align__(16) __nv_bfloat16 g_Clo[H_DIM * H_DIM];           // C lo
static __device__ float g_Asq[2][N_DIM * N_DIM];                              // squaring ping-pong
static __device__ float g_u[(size_t)B_DIM * H_DIM];                           // W^T x
static __device__ float g_z[(size_t)B_DIM * H_DIM];                           // current z (fp32)
static __device__ __align__(16) __nv_bfloat16 g_ah[2][(size_t)B_DIM * H_DIM]; // z_aux hi ping-pong
static __device__ __align__(16) __nv_bfloat16 g_al[2][(size_t)B_DIM * H_DIM]; // z_aux lo ping-pong
static __device__ float g_scal[8];   // [0]=ln accum, [3]=1/L, [4]=lam
static __device__ float g_w[16 * 24];

// ---------------- baseline PTX helpers (sm_80+: ldmatrix / mma.sync) ----------------
__device__ __forceinline__ uint32_t smem_u32(const void* p) {
    uint32_t a;
    asm("{ .reg .u64 t; cvta.to.shared.u64 t, %1; cvt.u32.u64 %0, t; }" : "=r"(a) : "l"(p));
    return a;
}
__device__ __forceinline__ void ldsm4(uint32_t& r0, uint32_t& r1, uint32_t& r2, uint32_t& r3,
                                      uint32_t addr) {
    asm volatile("ldmatrix.sync.aligned.m8n8.x4.shared.b16 {%0,%1,%2,%3}, [%4];"
                 : "=r"(r0), "=r"(r1), "=r"(r2), "=r"(r3) : "r"(addr));
}
__device__ __forceinline__ void mma16816(float* d, const uint32_t* a, uint32_t b0, uint32_t b1) {
    asm volatile(
        "mma.sync.aligned.m16n8k16.row.col.f32.bf16.bf16.f32 "
        "{%0,%1,%2,%3}, {%4,%5,%6,%7}, {%8,%9}, {%0,%1,%2,%3};"
        : "+f"(d[0]), "+f"(d[1]), "+f"(d[2]), "+f"(d[3])
        : "r"(a[0]), "r"(a[1]), "r"(a[2]), "r"(a[3]), "r"(b0), "r"(b1));
}

// ---------------- 20-op activation mixture ----------------
__device__ __forceinline__ float act_mix(float v, const float* aw, float lam) {
    float av  = fabsf(v);
    float e   = expf(-av);
    float i1e = 1.0f / (1.0f + e);
    float sig = (v >= 0.f) ? i1e : e * i1e;
    float sp  = fmaxf(v, 0.f) + log1pf(e);
    float e2  = e * e;
    float tha = (1.f - e2) / (1.f + e2);
    float th  = (v >= 0.f) ? tha : -tha;
    float oms = 1.f - sig;
    float q   = oms * oms;
    float msh = (1.f - q) / (1.f + q);
    float erv = erff(v * 0.70710678118654752f);
    float em1 = e - 1.f;
    float elu = (v > 0.f) ? v : em1;
    float r6  = fminf(fmaxf(v + 3.f, 0.f), 6.f) * (1.f / 6.f);
    float r;
    r  = aw[0]  * ((v > lam) ? (v - lam) : ((v < -lam) ? (v + lam) : 0.f));
    r += aw[1]  * fmaxf(v, 0.f);
    r += aw[2]  * v;
    r += aw[3]  * (0.5f * v * (1.f + erv));
    r += aw[4]  * elu;
    r += aw[5]  * ((av > lam) ? v : 0.f);
    r += aw[6]  * fminf(fmaxf(v, -1.f), 1.f);
    r += aw[7]  * (v * r6);
    r += aw[8]  * (1.0507009873554805f * ((v > 0.f) ? v : 1.6732632423543772f * em1));
    r += aw[9]  * elu;
    r += aw[10] * ((v >= 0.f) ? v : 0.01f * v);
    r += aw[11] * (v - sp);
    r += aw[12] * (v - th);
    r += aw[13] * (v / (1.f + av));
    r += aw[14] * sp;
    r += aw[15] * th;
    r += aw[16] * sig;
    r += aw[17] * r6;
    r += aw[18] * (v * sig);
    r += aw[19] * (v * msh);
    return r;
}

// ---------------- 64x64 SIMT GEMM pieces (spectral-norm chain) ----------------
__device__ __forceinline__ void ld64_T(float s[16][64], const float* src,
                                       int m0, int k0, int ld, int t) {
    int row = t >> 2, cv = (t & 3) * 4;
    float4 v = *(const float4*)&src[(size_t)(m0 + row) * ld + k0 + cv];
    s[cv + 0][row] = v.x; s[cv + 1][row] = v.y; s[cv + 2][row] = v.z; s[cv + 3][row] = v.w;
}
__device__ __forceinline__ void ld64_N(float s[16][64], const float* src,
                                       int k0, int n0, int ld, int t) {
    int row = t >> 4, cv = (t & 15) * 4;
    *(float4*)&s[row][cv] = *(const float4*)&src[(size_t)(k0 + row) * ld + n0 + cv];
}
__device__ __forceinline__ void mma64(const float (*a)[64], const float (*b)[64],
                                      int tx, int ty, float acc[4][4]) {
#pragma unroll
    for (int kk = 0; kk < 16; ++kk) {
        float ar[4], br[4];
        *(float4*)ar = *(const float4*)&a[kk][ty * 4];
        *(float4*)br = *(const float4*)&b[kk][tx * 4];
#pragma unroll
        for (int i = 0; i < 4; ++i)
#pragma unroll
            for (int j = 0; j < 4; ++j)
                acc[i][j] = fmaf(ar[i], br[j], acc[i][j]);
    }
}
// A0 = W W^T  [512x512], K=1024, 64 CTAs
__global__ __launch_bounds__(256) void k_wwT64(const float* __restrict__ W) {
    __shared__ float a[16][64], b[16][64];
    int t = threadIdx.x, tx = t & 15, ty = t >> 4;
    int n0 = blockIdx.x * 64, m0 = blockIdx.y * 64;
    float acc[4][4] = {};
    for (int k0 = 0; k0 < H_DIM; k0 += 16) {
        ld64_T(a, W, m0, k0, H_DIM, t);
        ld64_T(b, W, n0, k0, H_DIM, t);
        __syncthreads();
        mma64(a, b, tx, ty, acc);
        __syncthreads();
    }
#pragma unroll
    for (int i = 0; i < 4; ++i)
        *(float4*)&g_Asq[0][(size_t)(m0 + ty * 4 + i) * N_DIM + n0 + tx * 4] =
            make_float4(acc[i][0], acc[i][1], acc[i][2], acc[i][3]);
}
// fused: tr = trace(in); out = (in/tr)^2; block(0,0) accumulates ln(tr)*2^-j
__global__ __launch_bounds__(256) void k_sq64(int src, int j) {
    __shared__ float a[16][64], b[16][64];
    __shared__ float red[256];
    __shared__ float s_tr;
    const float* in = g_Asq[src];
    float* outp = g_Asq[src ^ 1];
    int t = threadIdx.x, tx = t & 15, ty = t >> 4;
    red[t] = in[(size_t)t * (N_DIM + 1)] + in[(size_t)(t + 256) * (N_DIM + 1)];
    __syncthreads();
    for (int s = 128; s > 0; s >>= 1) { if (t < s) red[t] += red[t + s]; __syncthreads(); }
    if (t == 0) {
        s_tr = red[0];
        if (blockIdx.x == 0 && blockIdx.y == 0) {
            float term = logf(red[0]) * ldexpf(1.f, -j);
            g_scal[0] = (j == 0) ? term : (g_scal[0] + term);
        }
    }
    __syncthreads();
    float inv = 1.f / s_tr;
    float sc = inv * inv;
    int n0 = blockIdx.x * 64, m0 = blockIdx.y * 64;
    float acc[4][4] = {};
    for (int k0 = 0; k0 < N_DIM; k0 += 16) {
        ld64_T(a, in, m0, k0, N_DIM, t);
        ld64_N(b, in, k0, n0, N_DIM, t);
        __syncthreads();
        mma64(a, b, tx, ty, acc);
        __syncthreads();
    }
#pragma unroll
    for (int i = 0; i < 4; ++i)
        *(float4*)&outp[(size_t)(m0 + ty * 4 + i) * N_DIM + n0 + tx * 4] =
            make_float4(acc[i][0] * sc, acc[i][1] * sc, acc[i][2] * sc, acc[i][3] * sc);
}
__global__ void k_finL() {
    __shared__ float red[512];
    int t = threadIdx.x;
    red[t] = g_Asq[0][(size_t)t * (N_DIM + 1)];
    __syncthreads();
    for (int s = 256; s > 0; s >>= 1) { if (t < s) red[t] += red[t + s]; __syncthreads(); }
    if (t == 0) {
        float lnL = g_scal[0] + logf(red[0]) * PINV;
        float L = expf(lnL);
        g_scal[3] = 1.f / L;
        g_scal[4] = 0.001f / L;
    }
}

// ---------------- 128x128 SIMT GEMM pieces (C and u, fp32, one-time) ----------------
__device__ __forceinline__ void load_A_T(float s[16][128], const float* src,
                                         int m0, int k0, int ld, int t) {
#pragma unroll
    for (int l = 0; l < 2; ++l) {
        int fid = t + l * 256;
        int row = fid >> 2, cv = (fid & 3) * 4;
        float4 v = *(const float4*)&src[(size_t)(m0 + row) * ld + k0 + cv];
        s[cv + 0][row] = v.x; s[cv + 1][row] = v.y;
        s[cv + 2][row] = v.z; s[cv + 3][row] = v.w;
    }
}
__device__ __forceinline__ void load_B_N(float s[16][128], const float* src,
                                         int k0, int n0, int ld, int t) {
#pragma unroll
    for (int l = 0; l < 2; ++l) {
        int fid = t + l * 256;
        int row = fid >> 5, cv = (fid & 31) * 4;
        *(float4*)&s[row][cv] = *(const float4*)&src[(size_t)(k0 + row) * ld + n0 + cv];
    }
}
__device__ __forceinline__ void mma_chunk(const float (*a_s)[128], const float (*b_s)[128],
                                          int tx, int ty, float acc[8][8]) {
#pragma unroll
    for (int kk = 0; kk < 16; ++kk) {
        float ar[8], br[8];
        *(float4*)&ar[0] = *(const float4*)&a_s[kk][ty * 8];
        *(float4*)&ar[4] = *(const float4*)&a_s[kk][ty * 8 + 4];
        *(float4*)&br[0] = *(const float4*)&b_s[kk][tx * 8];
        *(float4*)&br[4] = *(const float4*)&b_s[kk][tx * 8 + 4];
#pragma unroll
        for (int i = 0; i < 8; ++i)
#pragma unroll
            for (int j = 0; j < 8; ++j)
                acc[i][j] = fmaf(ar[i], br[j], acc[i][j]);
    }
}
__device__ __forceinline__ void store_tile(float* outp, int ldo, int m0, int n0,
                                           int tx, int ty, const float acc[8][8]) {
#pragma unroll
    for (int i = 0; i < 8; ++i) {
        size_t off = (size_t)(m0 + ty * 8 + i) * ldo + n0 + tx * 8;
        *(float4*)&outp[off]     = make_float4(acc[i][0], acc[i][1], acc[i][2], acc[i][3]);
        *(float4*)&outp[off + 4] = make_float4(acc[i][4], acc[i][5], acc[i][6], acc[i][7]);
    }
}
__global__ __launch_bounds__(256) void k_gemm_C(const float* __restrict__ W) {
    __shared__ float a_s[16][128], b_s[16][128];
    int t = threadIdx.x, tx = t & 15, ty = t >> 4;
    int n0 = blockIdx.x * 128, m0 = blockIdx.y * 128;
    float acc[8][8] = {};
    for (int k0 = 0; k0 < N_DIM; k0 += 16) {
        load_B_N(a_s, W, k0, m0, H_DIM, t);
        load_B_N(b_s, W, k0, n0, H_DIM, t);
        __syncthreads();
        mma_chunk(a_s, b_s, tx, ty, acc);
        __syncthreads();
    }
    store_tile(g_C, H_DIM, m0, n0, tx, ty, acc);
}
__global__ __launch_bounds__(256) void k_gemm_u(const float* __restrict__ x,
                                                const float* __restrict__ W) {
    __shared__ float a_s[16][128], b_s[16][128];
    int t = threadIdx.x, tx = t & 15, ty = t >> 4;
    int n0 = blockIdx.x * 128, m0 = blockIdx.y * 128;
    float acc[8][8] = {};
    for (int k0 = 0; k0 < N_DIM; k0 += 16) {
        load_A_T(a_s, x, m0, k0, N_DIM, t);
        load_B_N(b_s, W, k0, n0, H_DIM, t);
        __syncthreads();
        mma_chunk(a_s, b_s, tx, ty, acc);
        __syncthreads();
    }
    store_tile(g_u, H_DIM, m0, n0, tx, ty, acc);
}
__global__ void k_splitC() {
    int idx = blockIdx.x * 256 + threadIdx.x;
    float v = g_C[idx];
    __nv_bfloat16 h = __float2bfloat16(v);
    g_Chi[idx] = h;
    g_Clo[idx] = __float2bfloat16(v - __bfloat162float(h));
}
__global__ void k_weights(const float* __restrict__ alpha, const float* __restrict__ beta, int T) {
    int i = threadIdx.x;
    if (i >= T) return;
    float m = -1e30f;
    for (int k = 0; k < NOPS; ++k) m = fmaxf(m, alpha[i * NOPS + k]);
    float e[NOPS], s = 0.f;
    for (int k = 0; k < NOPS; ++k) { e[k] = expf(alpha[i * NOPS + k] - m); s += e[k]; }
    float invs = 1.f / s;
    for (int k = 0; k < NOPS; ++k) g_w[i * 24 + k] = e[k] * invs;
    float b0 = beta[i * 2], b1 = beta[i * 2 + 1];
    float mb = fmaxf(b0, b1);
    float e0 = expf(b0 - mb), e1 = expf(b1 - mb);
    float ib = 1.f / (e0 + e1);
    g_w[i * 24 + 20] = e0 * ib;
    g_w[i * 24 + 21] = e1 * ib;
}
// iteration 0: z_g = u/L elementwise; emits z and z_aux(hi/lo) for iter 1
__global__ void k_iter0(float* outF) {
    __shared__ float smw[24];
    int t = threadIdx.x;
    if (t < 22) smw[t] = g_w[t];
    __syncthreads();
    float invL = g_scal[3], lam = g_scal[4];
    float bw1 = smw[21];
    float mom1 = 0.25f;                      // momentum of iter 1 = 1/(1+3)
    float ca = 1.f + mom1 * (1.f - bw1);     // z_aux_1 = ca * zop  (z=0)
    size_t idx = ((size_t)blockIdx.x * 256 + t) * 4;
    float4 uu = *(const float4*)&g_u[idx];
    float zo[4];
    zo[0] = act_mix(uu.x * invL, smw, lam);
    zo[1] = act_mix(uu.y * invL, smw, lam);
    zo[2] = act_mix(uu.z * invL, smw, lam);
    zo[3] = act_mix(uu.w * invL, smw, lam);
    if (outF) {
        *(float4*)&outF[idx] = make_float4(zo[0], zo[1], zo[2], zo[3]);
    } else {
        *(float4*)&g_z[idx] = make_float4(zo[0], zo[1], zo[2], zo[3]);
#pragma unroll
        for (int j = 0; j < 4; ++j) {
            float za = ca * zo[j];
            __nv_bfloat16 h = __float2bfloat16(za);
            g_ah[0][idx + j] = h;
            g_al[0][idx + j] = __float2bfloat16(za - __bfloat162float(h));
        }
    }
}

// ---------------- mma.sync fused iteration: D = z_aux * C (bf16 split-3) + epilogue ----------------
// grid (8, 32): n0 = bx*128 (H), m0 = by*128 (B). 256 threads (8 warps, 2x4), 2 CTAs/SM.
__global__ __launch_bounds__(256, 2) void k_mma_iter(int inSel, int outSel, float* outF,
                                                     int iter, float mom_next, int is_last) {
    extern __shared__ char dsm[];
    __shared__ float smw[24];

    const __nv_bfloat16* __restrict__ ah = g_ah[inSel];
    const __nv_bfloat16* __restrict__ al = g_al[inSel];
    __nv_bfloat16* __restrict__ aho = g_ah[outSel];
    __nv_bfloat16* __restrict__ alo = g_al[outSel];

    int tid = threadIdx.x, wid = tid >> 5, lane = tid & 31;
    int m0 = blockIdx.y * 128, n0 = blockIdx.x * 128;
    int wm = (wid >> 2) * 64;        // warp M offset (0/64)
    int wn = (wid & 3) * 32;         // warp N offset (0/32/64/96)

    char* tp = (char*)(((uintptr_t)dsm + 1023) & ~(uintptr_t)1023);
    char* sAh = tp;
    char* sAl = tp + 16384;
    char* sBh = tp + 32768;
    char* sBl = tp + 49152;
    uint32_t bAh = smem_u32(sAh), bAl = smem_u32(sAl);
    uint32_t bBh = smem_u32(sBh), bBl = smem_u32(sBl);

    if (tid < 22) smw[tid] = g_w[iter * 24 + tid];

    const uint4* pAH = (const uint4*)ah;
    const uint4* pAL = (const uint4*)al;
    const uint4* pBH = (const uint4*)g_Chi;
    const uint4* pBL = (const uint4*)g_Clo;

    float acc[4][4][4];              // [mt][nt][e]
#pragma unroll
    for (int a = 0; a < 4; ++a)
#pragma unroll
        for (int b = 0; b < 4; ++b)
#pragma unroll
            for (int e = 0; e < 4; ++e) acc[a][b][e] = 0.f;

    // store-side mapping (per thread, 4 vectors per tile)
    int srow[4], sgrp[4];
    uint32_t ssw[4];
#pragma unroll
    for (int j = 0; j < 4; ++j) {
        int s = tid + j * 256;
        srow[j] = s >> 3; sgrp[j] = s & 7;
        uint32_t off = (uint32_t)(srow[j] * 128 + sgrp[j] * 16);
        ssw[j] = off ^ ((off >> 3) & 0x70);
    }
    // ldmatrix lane mapping
    int lr = lane & 15;              // row within 16
    int lk = (lane >> 4) * 16;       // byte offset along K within k16 (0 or 16)

    for (int c = 0; c < NCH; ++c) {
        if (c) __syncthreads();      // protect previous chunk's smem reads
        int k8 = c * 8;              // uint4 index along K (64 bf16 = 8 uint4)
#pragma unroll
        for (int j = 0; j < 4; ++j) {
            size_t gA = (size_t)(m0 + srow[j]) * (H_DIM / 8) + k8 + sgrp[j];
            size_t gB = (size_t)(n0 + srow[j]) * (H_DIM / 8) + k8 + sgrp[j];
            *(uint4*)(sAh + ssw[j]) = pAH[gA];
            *(uint4*)(sAl + ssw[j]) = pAL[gA];
            *(uint4*)(sBh + ssw[j]) = pBH[gB];
            *(uint4*)(sBl + ssw[j]) = pBL[gB];
        }
        __syncthreads();
#pragma unroll
        for (int ks = 0; ks < 4; ++ks) {
            // ---- B fragments: 4 n-tiles x (k0-7, k8-15), hi & lo ----
            uint32_t bh0[4], bh1[4], bl0[4], bl1[4];
#pragma unroll
            for (int np = 0; np < 2; ++np) {
                uint32_t off = (uint32_t)((wn + np * 16 + lr) * 128 + ks * 32 + lk);
                uint32_t sw = off ^ ((off >> 3) & 0x70);
                uint32_t r0, r1, r2, r3;
                ldsm4(r0, r1, r2, r3, bBh + sw);
                bh0[np * 2] = r0; bh0[np * 2 + 1] = r1;
                bh1[np * 2] = r2; bh1[np * 2 + 1] = r3;
                ldsm4(r0, r1, r2, r3, bBl + sw);
                bl0[np * 2] = r0; bl0[np * 2 + 1] = r1;
                bl1[np * 2] = r2; bl1[np * 2 + 1] = r3;
            }
#pragma unroll
            for (int mt = 0; mt < 4; ++mt) {
                uint32_t off = (uint32_t)((wm + mt * 16 + lr) * 128 + ks * 32 + lk);
                uint32_t sw = off ^ ((off >> 3) & 0x70);
                uint32_t a_h[4], a_l[4];
                ldsm4(a_h[0], a_h[1], a_h[2], a_h[3], bAh + sw);
                ldsm4(a_l[0], a_l[1], a_l[2], a_l[3], bAl + sw);
#pragma unroll
                for (int nt = 0; nt < 4; ++nt) {
                    mma16816(acc[mt][nt], a_h, bh0[nt], bh1[nt]);   // ah*bh
                    mma16816(acc[mt][nt], a_h, bl0[nt], bl1[nt]);   // ah*bl
                    mma16816(acc[mt][nt], a_l, bh0[nt], bh1[nt]);   // al*bh
                }
            }
        }
    }

    // ---- fused epilogue straight from register accumulators ----
    float invL = g_scal[3], lam = g_scal[4];
    float bw0 = smw[20], bw1 = smw[21];
    float ca = 1.f + mom_next * (1.f - bw1);
    float cb = mom_next * bw0;
    int rbase = lane >> 2, cpair = (lane & 3) * 2;
#pragma unroll
    for (int mt = 0; mt < 4; ++mt) {
#pragma unroll
        for (int e2 = 0; e2 < 2; ++e2) {
            int m = m0 + wm + mt * 16 + rbase + e2 * 8;
            size_t rowoff = (size_t)m * H_DIM;
#pragma unroll
            for (int nt = 0; nt < 4; ++nt) {
                size_t idx = rowoff + n0 + wn + nt * 8 + cpair;
                float d0 = acc[mt][nt][e2 * 2 + 0];
                float d1 = acc[mt][nt][e2 * 2 + 1];
                __nv_bfloat162 h2 = *(const __nv_bfloat162*)&ah[idx];
                __nv_bfloat162 l2 = *(const __nv_bfloat162*)&al[idx];
                float2 u2 = *(const float2*)&g_u[idx];
                float za0 = __bfloat162float(h2.x) + __bfloat162float(l2.x);
                float za1 = __bfloat162float(h2.y) + __bfloat162float(l2.y);
                float zg0 = za0 - (d0 - u2.x) * invL;
                float zg1 = za1 - (d1 - u2.y) * invL;
                float zop0 = act_mix(zg0, smw, lam);
                float zop1 = act_mix(zg1, smw, lam);
                if (is_last) {
                    *(float2*)&outF[idx] = make_float2(zop0, zop1);
                } else {
                    float2 z2 = *(const float2*)&g_z[idx];
                    *(float2*)&g_z[idx] = make_float2(zop0, zop1);
                    float zan0 = ca * zop0 - cb * z2.x;
                    float zan1 = ca * zop1 - cb * z2.y;
                    __nv_bfloat162 ho, lo2;
                    ho.x = __float2bfloat16(zan0);
                    ho.y = __float2bfloat16(zan1);
                    lo2.x = __float2bfloat16(zan0 - __bfloat162float(ho.x));
                    lo2.y = __float2bfloat16(zan1 - __bfloat162float(ho.y));
                    *(__nv_bfloat162*)&aho[idx] = ho;
                    *(__nv_bfloat162*)&alo[idx] = lo2;
                }
            }
        }
    }
}

// ---------------- host orchestration (graph-capturable: kernel launches only) ----------------
extern "C" void kernel_launch(void* const* d_in, const int* in_sizes, int n_in,
                              void* d_out, int out_size) {
    const float* x     = (const float*)d_in[0];
    const float* W     = (const float*)d_in[1];
    const float* alpha = (const float*)d_in[2];
    const float* lbeta = (const float*)d_in[3];
    float* out = (float*)d_out;
    int T = in_sizes[2] / NOPS;
    if (T < 1) T = 1;
    if (T > 16) T = 16;

    const int DSM = 65536 + 1024;   // 4 x 16KB bf16 tiles + align slack
    cudaFuncSetAttribute(k_mma_iter, cudaFuncAttributeMaxDynamicSharedMemorySize, DSM);

    dim3 thr(256);

    // Spectral norm: A0 = WW^T, 12 trace-normalized squarings (trace fused in-kernel)
    k_wwT64<<<dim3(8, 8), thr>>>(W);
    for (int j = 0; j < PWRK; ++j)
        k_sq64<<<dim3(8, 8), thr>>>(j & 1, j);
    k_finL<<<1, 512>>>();

    // One-time precomputes
    k_gemm_C<<<dim3(8, 8), thr>>>(W);
    k_splitC<<<(H_DIM * H_DIM) / 256, thr>>>();
    k_gemm_u<<<dim3(8, 32), thr>>>(x, W);
    k_weights<<<1, 32>>>(alpha, lbeta, T);

    // Iteration 0 (z = zprev = 0): elementwise
    k_iter0<<<(B_DIM * H_DIM) / (256 * 4), thr>>>((T == 1) ? out : nullptr);

    // Iterations 1..T-1: mma.sync fused GEMM + epilogue
    for (int i = 1; i < T; ++i) {
        float mom_next = (float)((double)(i + 1) / (double)(i + 4));
        int inSel  = (i + 1) & 1;
        int outSel = i & 1;
        int last = (i == T - 1);
        k_mma_iter<<<dim3(8, 32), thr, DSM>>>(inSel, outSel, last ? out : nullptr,
                                              i, mom_next, last);
    }
}

// round 12
// speedup vs baseline: 1.9834x; 1.2376x over previous
#include <cuda_runtime.h>
#include <cuda_bf16.h>
#include <math.h>
#include <stdint.h>

#define B_DIM 4096
#define N_DIM 512
#define H_DIM 1024
#define NOPS  20
#define PWRK  12               // squarings -> p = 2^12 = 4096
#define PINV  (1.0f/4096.0f)
#define KC2   32               // K chunk (bf16 cols) per stage, iteration GEMM
#define NCH2  (H_DIM / KC2)    // 32 chunks

#define SW128(o) ((o) ^ (((o) >> 3) & 0x70))
#define SW64(o)  ((o) ^ (((o) >> 3) & 0x30))

// ---------------- static device scratch (no allocations allowed) ----------------
static __device__ float g_C[H_DIM * H_DIM];                                   // W^T W fp32
static __device__ __align__(16) __nv_bfloat16 g_Chi[H_DIM * H_DIM];           // C hi
static __device__ __align__(16) __nv_bfloat16 g_Clo[H_DIM * H_DIM];           // C lo
static __device__ __align__(16) __nv_bfloat16 g_sAh[2][N_DIM * N_DIM];        // squaring A hi ping-pong
static __device__ __align__(16) __nv_bfloat16 g_sAl[2][N_DIM * N_DIM];        // squaring A lo ping-pong
static __device__ float g_u[(size_t)B_DIM * H_DIM];                           // W^T x
static __device__ float g_z[(size_t)B_DIM * H_DIM];                           // current z (fp32)
static __device__ __align__(16) __nv_bfloat16 g_ah[2][(size_t)B_DIM * H_DIM]; // z_aux hi ping-pong
static __device__ __align__(16) __nv_bfloat16 g_al[2][(size_t)B_DIM * H_DIM]; // z_aux lo ping-pong
static __device__ float g_scal[8];   // [0]=ln accum, [3]=1/L, [4]=lam
static __device__ float g_w[16 * 24];

// ---------------- baseline PTX helpers (sm_80+: ldmatrix / mma.sync / cp.async) --------
__device__ __forceinline__ uint32_t smem_u32(const void* p) {
    uint32_t a;
    asm("{ .reg .u64 t; cvta.to.shared.u64 t, %1; cvt.u32.u64 %0, t; }" : "=r"(a) : "l"(p));
    return a;
}
__device__ __forceinline__ void ldsm4(uint32_t& r0, uint32_t& r1, uint32_t& r2, uint32_t& r3,
                                      uint32_t addr) {
    asm volatile("ldmatrix.sync.aligned.m8n8.x4.shared.b16 {%0,%1,%2,%3}, [%4];"
                 : "=r"(r0), "=r"(r1), "=r"(r2), "=r"(r3) : "r"(addr));
}
__device__ __forceinline__ void mma16816(float* d, const uint32_t* a, uint32_t b0, uint32_t b1) {
    asm volatile(
        "mma.sync.aligned.m16n8k16.row.col.f32.bf16.bf16.f32 "
        "{%0,%1,%2,%3}, {%4,%5,%6,%7}, {%8,%9}, {%0,%1,%2,%3};"
        : "+f"(d[0]), "+f"(d[1]), "+f"(d[2]), "+f"(d[3])
        : "r"(a[0]), "r"(a[1]), "r"(a[2]), "r"(a[3]), "r"(b0), "r"(b1));
}
#define CP_A16(dst, src) asm volatile("cp.async.cg.shared.global [%0], [%1], 16;" :: "r"(dst), "l"(src))
#define CP_COMMIT()      asm volatile("cp.async.commit_group;" ::: "memory")
#define CP_WAIT(n)       asm volatile("cp.async.wait_group %0;" :: "n"(n) : "memory")

// ---------------- 20-op activation mixture ----------------
__device__ __forceinline__ float act_mix(float v, const float* aw, float lam) {
    float av  = fabsf(v);
    float e   = expf(-av);
    float i1e = 1.0f / (1.0f + e);
    float sig = (v >= 0.f) ? i1e : e * i1e;
    float sp  = fmaxf(v, 0.f) + log1pf(e);
    float e2  = e * e;
    float tha = (1.f - e2) / (1.f + e2);
    float th  = (v >= 0.f) ? tha : -tha;
    float oms = 1.f - sig;
    float q   = oms * oms;
    float msh = (1.f - q) / (1.f + q);
    float erv = erff(v * 0.70710678118654752f);
    float em1 = e - 1.f;
    float elu = (v > 0.f) ? v : em1;
    float r6  = fminf(fmaxf(v + 3.f, 0.f), 6.f) * (1.f / 6.f);
    float r;
    r  = aw[0]  * ((v > lam) ? (v - lam) : ((v < -lam) ? (v + lam) : 0.f));
    r += aw[1]  * fmaxf(v, 0.f);
    r += aw[2]  * v;
    r += aw[3]  * (0.5f * v * (1.f + erv));
    r += aw[4]  * elu;
    r += aw[5]  * ((av > lam) ? v : 0.f);
    r += aw[6]  * fminf(fmaxf(v, -1.f), 1.f);
    r += aw[7]  * (v * r6);
    r += aw[8]  * (1.0507009873554805f * ((v > 0.f) ? v : 1.6732632423543772f * em1));
    r += aw[9]  * elu;
    r += aw[10] * ((v >= 0.f) ? v : 0.01f * v);
    r += aw[11] * (v - sp);
    r += aw[12] * (v - th);
    r += aw[13] * (v / (1.f + av));
    r += aw[14] * sp;
    r += aw[15] * th;
    r += aw[16] * sig;
    r += aw[17] * r6;
    r += aw[18] * (v * sig);
    r += aw[19] * (v * msh);
    return r;
}

// ---------------- A0 = W W^T [512x512], fp32 SIMT, epilogue emits bf16 hi/lo ----------------
__device__ __forceinline__ void ld64_T(float s[16][64], const float* src,
                                       int m0, int k0, int ld, int t) {
    int row = t >> 2, cv = (t & 3) * 4;
    float4 v = *(const float4*)&src[(size_t)(m0 + row) * ld + k0 + cv];
    s[cv + 0][row] = v.x; s[cv + 1][row] = v.y; s[cv + 2][row] = v.z; s[cv + 3][row] = v.w;
}
__device__ __forceinline__ void mma64(const float (*a)[64], const float (*b)[64],
                                      int tx, int ty, float acc[4][4]) {
#pragma unroll
    for (int kk = 0; kk < 16; ++kk) {
        float ar[4], br[4];
        *(float4*)ar = *(const float4*)&a[kk][ty * 4];
        *(float4*)br = *(const float4*)&b[kk][tx * 4];
#pragma unroll
        for (int i = 0; i < 4; ++i)
#pragma unroll
            for (int j = 0; j < 4; ++j)
                acc[i][j] = fmaf(ar[i], br[j], acc[i][j]);
    }
}
__global__ __launch_bounds__(256) void k_wwT64(const float* __restrict__ W) {
    __shared__ float a[16][64], b[16][64];
    int t = threadIdx.x, tx = t & 15, ty = t >> 4;
    int n0 = blockIdx.x * 64, m0 = blockIdx.y * 64;
    float acc[4][4] = {};
    for (int k0 = 0; k0 < H_DIM; k0 += 16) {
        ld64_T(a, W, m0, k0, H_DIM, t);
        ld64_T(b, W, n0, k0, H_DIM, t);
        __syncthreads();
        mma64(a, b, tx, ty, acc);
        __syncthreads();
    }
#pragma unroll
    for (int i = 0; i < 4; ++i)
#pragma unroll
        for (int j = 0; j < 4; ++j) {
            float v = acc[i][j];
            size_t o = (size_t)(m0 + ty * 4 + i) * N_DIM + n0 + tx * 4 + j;
            __nv_bfloat16 h = __float2bfloat16(v);
            g_sAh[0][o] = h;
            g_sAl[0][o] = __float2bfloat16(v - __bfloat162float(h));
        }
}

// ---------------- squaring via mma.sync: out = (in/tr)^2, bf16 split-4, trace fused ------
// grid (8,8) of 64x64 tiles; 128 threads (4 warps, warp tile 32x32)
__global__ __launch_bounds__(128) void k_sqmma(int src, int j) {
    __shared__ __align__(16) char sm[32768];    // Ah 8K | Al 8K | Bh 8K | Bl 8K
    __shared__ float red[128];
    __shared__ float s_tr;
    const __nv_bfloat16* Ah = g_sAh[src];
    const __nv_bfloat16* Al = g_sAl[src];
    __nv_bfloat16* Oh = g_sAh[src ^ 1];
    __nv_bfloat16* Ol = g_sAl[src ^ 1];
    int tid = threadIdx.x, wid = tid >> 5, lane = tid & 31;
    int m0 = blockIdx.y * 64, n0 = blockIdx.x * 64;
    int wm = (wid >> 1) * 32, wn = (wid & 1) * 32;

    // trace of input (hi+lo diag), redundant per CTA
    float ts = 0.f;
#pragma unroll
    for (int i = 0; i < 4; ++i) {
        int d = tid * 4 + i;
        ts += __bfloat162float(Ah[(size_t)d * (N_DIM + 1)]) +
              __bfloat162float(Al[(size_t)d * (N_DIM + 1)]);
    }
    red[tid] = ts;
    __syncthreads();
    for (int s = 64; s > 0; s >>= 1) { if (tid < s) red[tid] += red[tid + s]; __syncthreads(); }
    if (tid == 0) {
        s_tr = red[0];
        if (blockIdx.x == 0 && blockIdx.y == 0) {
            float term = logf(red[0]) * ldexpf(1.f, -j);
            g_scal[0] = (j == 0) ? term : (g_scal[0] + term);
        }
    }

    uint32_t bAh = smem_u32(sm), bAl = bAh + 8192, bBh = bAh + 16384, bBl = bAh + 24576;
    const uint4* pAh = (const uint4*)Ah;
    const uint4* pAl = (const uint4*)Al;

    float acc[2][4][4];
#pragma unroll
    for (int a = 0; a < 2; ++a)
#pragma unroll
        for (int b = 0; b < 4; ++b)
#pragma unroll
            for (int e = 0; e < 4; ++e) acc[a][b][e] = 0.f;

    int lr = lane & 15, lk = (lane >> 4) * 16;
    for (int c = 0; c < 8; ++c) {               // K=512 in chunks of 64
        __syncthreads();
#pragma unroll
        for (int jj = 0; jj < 4; ++jj) {        // 4 granules per thread per tile
            int s = tid + jj * 128;
            int row = s >> 3, g = s & 7;
            uint32_t sw = SW128((uint32_t)(row * 128 + g * 16));
            size_t gi = (size_t)(m0 + row) * 64 + c * 8 + g;   // A rows (m)
            size_t gj = (size_t)(n0 + row) * 64 + c * 8 + g;   // B rows (n); A symmetric
            *(uint4*)(sm + sw)          = pAh[gi];
            *(uint4*)(sm + 8192 + sw)   = pAl[gi];
            *(uint4*)(sm + 16384 + sw)  = pAh[gj];
            *(uint4*)(sm + 24576 + sw)  = pAl[gj];
        }
        __syncthreads();
#pragma unroll
        for (int ks = 0; ks < 4; ++ks) {
            uint32_t bh0[4], bh1[4], bl0[4], bl1[4];
#pragma unroll
            for (int np = 0; np < 2; ++np) {
                uint32_t sw = SW128((uint32_t)((wn + np * 16 + lr) * 128 + ks * 32 + lk));
                uint32_t r0, r1, r2, r3;
                ldsm4(r0, r1, r2, r3, bBh + sw);
                bh0[np * 2] = r0; bh0[np * 2 + 1] = r1; bh1[np * 2] = r2; bh1[np * 2 + 1] = r3;
                ldsm4(r0, r1, r2, r3, bBl + sw);
                bl0[np * 2] = r0; bl0[np * 2 + 1] = r1; bl1[np * 2] = r2; bl1[np * 2 + 1] = r3;
            }
#pragma unroll
            for (int mt = 0; mt < 2; ++mt) {
                uint32_t sw = SW128((uint32_t)((wm + mt * 16 + lr) * 128 + ks * 32 + lk));
                uint32_t a_h[4], a_l[4];
                ldsm4(a_h[0], a_h[1], a_h[2], a_h[3], bAh + sw);
                ldsm4(a_l[0], a_l[1], a_l[2], a_l[3], bAl + sw);
#pragma unroll
                for (int nt = 0; nt < 4; ++nt) {
                    mma16816(acc[mt][nt], a_h, bh0[nt], bh1[nt]);
                    mma16816(acc[mt][nt], a_h, bl0[nt], bl1[nt]);
                    mma16816(acc[mt][nt], a_l, bh0[nt], bh1[nt]);
                    mma16816(acc[mt][nt], a_l, bl0[nt], bl1[nt]);   // 4th term: chain accuracy
                }
            }
        }
    }
    float sc = 1.f / (s_tr * s_tr);
    int rbase = lane >> 2, cpair = (lane & 3) * 2;
#pragma unroll
    for (int mt = 0; mt < 2; ++mt)
#pragma unroll
        for (int e2 = 0; e2 < 2; ++e2) {
            int m = m0 + wm + mt * 16 + rbase + e2 * 8;
#pragma unroll
            for (int nt = 0; nt < 4; ++nt) {
                size_t idx = (size_t)m * N_DIM + n0 + wn + nt * 8 + cpair;
                float v0 = acc[mt][nt][e2 * 2 + 0] * sc;
                float v1 = acc[mt][nt][e2 * 2 + 1] * sc;
                __nv_bfloat162 h2, l2;
                h2.x = __float2bfloat16(v0); h2.y = __float2bfloat16(v1);
                l2.x = __float2bfloat16(v0 - __bfloat162float(h2.x));
                l2.y = __float2bfloat16(v1 - __bfloat162float(h2.y));
                *(__nv_bfloat162*)&Oh[idx] = h2;
                *(__nv_bfloat162*)&Ol[idx] = l2;
            }
        }
}
__global__ void k_finL() {
    __shared__ float red[512];
    int t = threadIdx.x;
    red[t] = __bfloat162float(g_sAh[0][(size_t)t * (N_DIM + 1)]) +
             __bfloat162float(g_sAl[0][(size_t)t * (N_DIM + 1)]);
    __syncthreads();
    for (int s = 256; s > 0; s >>= 1) { if (t < s) red[t] += red[t + s]; __syncthreads(); }
    if (t == 0) {
        float lnL = g_scal[0] + logf(red[0]) * PINV;
        float L = expf(lnL);
        g_scal[3] = 1.f / L;
        g_scal[4] = 0.001f / L;
    }
}

// ---------------- 128x128 SIMT fp32 GEMMs (C and u, one-time) ----------------
__device__ __forceinline__ void load_A_T(float s[16][128], const float* src,
                                         int m0, int k0, int ld, int t) {
#pragma unroll
    for (int l = 0; l < 2; ++l) {
        int fid = t + l * 256;
        int row = fid >> 2, cv = (fid & 3) * 4;
        float4 v = *(const float4*)&src[(size_t)(m0 + row) * ld + k0 + cv];
        s[cv + 0][row] = v.x; s[cv + 1][row] = v.y;
        s[cv + 2][row] = v.z; s[cv + 3][row] = v.w;
    }
}
__device__ __forceinline__ void load_B_N(float s[16][128], const float* src,
                                         int k0, int n0, int ld, int t) {
#pragma unroll
    for (int l = 0; l < 2; ++l) {
        int fid = t + l * 256;
        int row = fid >> 5, cv = (fid & 31) * 4;
        *(float4*)&s[row][cv] = *(const float4*)&src[(size_t)(k0 + row) * ld + n0 + cv];
    }
}
__device__ __forceinline__ void mma_chunk(const float (*a_s)[128], const float (*b_s)[128],
                                          int tx, int ty, float acc[8][8]) {
#pragma unroll
    for (int kk = 0; kk < 16; ++kk) {
        float ar[8], br[8];
        *(float4*)&ar[0] = *(const float4*)&a_s[kk][ty * 8];
        *(float4*)&ar[4] = *(const float4*)&a_s[kk][ty * 8 + 4];
        *(float4*)&br[0] = *(const float4*)&b_s[kk][tx * 8];
        *(float4*)&br[4] = *(const float4*)&b_s[kk][tx * 8 + 4];
#pragma unroll
        for (int i = 0; i < 8; ++i)
#pragma unroll
            for (int j = 0; j < 8; ++j)
                acc[i][j] = fmaf(ar[i], br[j], acc[i][j]);
    }
}
__device__ __forceinline__ void store_tile(float* outp, int ldo, int m0, int n0,
                                           int tx, int ty, const float acc[8][8]) {
#pragma unroll
    for (int i = 0; i < 8; ++i) {
        size_t off = (size_t)(m0 + ty * 8 + i) * ldo + n0 + tx * 8;
        *(float4*)&outp[off]     = make_float4(acc[i][0], acc[i][1], acc[i][2], acc[i][3]);
        *(float4*)&outp[off + 4] = make_float4(acc[i][4], acc[i][5], acc[i][6], acc[i][7]);
    }
}
__global__ __launch_bounds__(256) void k_gemm_C(const float* __restrict__ W) {
    __shared__ float a_s[16][128], b_s[16][128];
    int t = threadIdx.x, tx = t & 15, ty = t >> 4;
    int n0 = blockIdx.x * 128, m0 = blockIdx.y * 128;
    float acc[8][8] = {};
    for (int k0 = 0; k0 < N_DIM; k0 += 16) {
        load_B_N(a_s, W, k0, m0, H_DIM, t);
        load_B_N(b_s, W, k0, n0, H_DIM, t);
        __syncthreads();
        mma_chunk(a_s, b_s, tx, ty, acc);
        __syncthreads();
    }
    store_tile(g_C, H_DIM, m0, n0, tx, ty, acc);
}
__global__ __launch_bounds__(256) void k_gemm_u(const float* __restrict__ x,
                                                const float* __restrict__ W) {
    __shared__ float a_s[16][128], b_s[16][128];
    int t = threadIdx.x, tx = t & 15, ty = t >> 4;
    int n0 = blockIdx.x * 128, m0 = blockIdx.y * 128;
    float acc[8][8] = {};
    for (int k0 = 0; k0 < N_DIM; k0 += 16) {
        load_A_T(a_s, x, m0, k0, N_DIM, t);
        load_B_N(b_s, W, k0, n0, H_DIM, t);
        __syncthreads();
        mma_chunk(a_s, b_s, tx, ty, acc);
        __syncthreads();
    }
    store_tile(g_u, H_DIM, m0, n0, tx, ty, acc);
}
__global__ void k_splitC() {
    int idx = blockIdx.x * 256 + threadIdx.x;
    float v = g_C[idx];
    __nv_bfloat16 h = __float2bfloat16(v);
    g_Chi[idx] = h;
    g_Clo[idx] = __float2bfloat16(v - __bfloat162float(h));
}
__global__ void k_weights(const float* __restrict__ alpha, const float* __restrict__ beta, int T) {
    int i = threadIdx.x;
    if (i >= T) return;
    float m = -1e30f;
    for (int k = 0; k < NOPS; ++k) m = fmaxf(m, alpha[i * NOPS + k]);
    float e[NOPS], s = 0.f;
    for (int k = 0; k < NOPS; ++k) { e[k] = expf(alpha[i * NOPS + k] - m); s += e[k]; }
    float invs = 1.f / s;
    for (int k = 0; k < NOPS; ++k) g_w[i * 24 + k] = e[k] * invs;
    float b0 = beta[i * 2], b1 = beta[i * 2 + 1];
    float mb = fmaxf(b0, b1);
    float e0 = expf(b0 - mb), e1 = expf(b1 - mb);
    float ib = 1.f / (e0 + e1);
    g_w[i * 24 + 20] = e0 * ib;
    g_w[i * 24 + 21] = e1 * ib;
}
// iteration 0: z_g = u/L elementwise; emits z and z_aux(hi/lo) for iter 1
__global__ void k_iter0(float* outF) {
    __shared__ float smw[24];
    int t = threadIdx.x;
    if (t < 22) smw[t] = g_w[t];
    __syncthreads();
    float invL = g_scal[3], lam = g_scal[4];
    float bw1 = smw[21];
    float mom1 = 0.25f;
    float ca = 1.f + mom1 * (1.f - bw1);
    size_t idx = ((size_t)blockIdx.x * 256 + t) * 4;
    float4 uu = *(const float4*)&g_u[idx];
    float zo[4];
    zo[0] = act_mix(uu.x * invL, smw, lam);
    zo[1] = act_mix(uu.y * invL, smw, lam);
    zo[2] = act_mix(uu.z * invL, smw, lam);
    zo[3] = act_mix(uu.w * invL, smw, lam);
    if (outF) {
        *(float4*)&outF[idx] = make_float4(zo[0], zo[1], zo[2], zo[3]);
    } else {
        *(float4*)&g_z[idx] = make_float4(zo[0], zo[1], zo[2], zo[3]);
#pragma unroll
        for (int j = 0; j < 4; ++j) {
            float za = ca * zo[j];
            __nv_bfloat16 h = __float2bfloat16(za);
            g_ah[0][idx + j] = h;
            g_al[0][idx + j] = __float2bfloat16(za - __bfloat162float(h));
        }
    }
}

// ---------------- mma.sync fused iteration, cp.async double-buffered -------------------
// grid (8, 32): n0 = bx*128 (H), m0 = by*128 (B). 256 threads (8 warps, 2x4), 2 CTAs/SM.
// Stage = 32 K-cols: Ah 8K | Al 8K | Bh 8K | Bl 8K = 32KB; 2 stages = 64KB.
__global__ __launch_bounds__(256, 2) void k_mma_iter(int inSel, int outSel, float* outF,
                                                     int iter, float mom_next, int is_last) {
    extern __shared__ char dsm[];
    __shared__ float smw[24];

    const __nv_bfloat16* __restrict__ ah = g_ah[inSel];
    const __nv_bfloat16* __restrict__ al = g_al[inSel];
    __nv_bfloat16* __restrict__ aho = g_ah[outSel];
    __nv_bfloat16* __restrict__ alo = g_al[outSel];

    int tid = threadIdx.x, wid = tid >> 5, lane = tid & 31;
    int m0 = blockIdx.y * 128, n0 = blockIdx.x * 128;
    int wm = (wid >> 2) * 64;        // warp M offset (0/64)
    int wn = (wid & 3) * 32;         // warp N offset (0/32/64/96)

    char* tp = (char*)(((uintptr_t)dsm + 1023) & ~(uintptr_t)1023);
    uint32_t base = smem_u32(tp);

    if (tid < 22) smw[tid] = g_w[iter * 24 + tid];

    const uint4* pAH = (const uint4*)ah;
    const uint4* pAL = (const uint4*)al;
    const uint4* pBH = (const uint4*)g_Chi;
    const uint4* pBL = (const uint4*)g_Clo;

    float acc[4][4][4];
#pragma unroll
    for (int a = 0; a < 4; ++a)
#pragma unroll
        for (int b = 0; b < 4; ++b)
#pragma unroll
            for (int e = 0; e < 4; ++e) acc[a][b][e] = 0.f;

    // per-thread store mapping: 2 granules per tile per stage (128 rows x 4 granules of 16B)
    int lrow[2], lg[2];
    uint32_t lsw[2];
#pragma unroll
    for (int j = 0; j < 2; ++j) {
        int s = tid + j * 256;
        lrow[j] = s >> 2; lg[j] = s & 3;
        lsw[j] = SW64((uint32_t)(lrow[j] * 64 + lg[j] * 16));
    }
    int lr = lane & 15, lk = (lane >> 4) * 16;

    // prologue: load chunk 0 into stage 0
#pragma unroll
    for (int j = 0; j < 2; ++j) {
        size_t gA = (size_t)(m0 + lrow[j]) * (H_DIM / 8) + lg[j];
        size_t gB = (size_t)(n0 + lrow[j]) * (H_DIM / 8) + lg[j];
        CP_A16(base + lsw[j],          (const void*)(pAH + gA));
        CP_A16(base + 8192  + lsw[j],  (const void*)(pAL + gA));
        CP_A16(base + 16384 + lsw[j],  (const void*)(pBH + gB));
        CP_A16(base + 24576 + lsw[j],  (const void*)(pBL + gB));
    }
    CP_COMMIT();

    for (int c = 0; c < NCH2; ++c) {
        uint32_t sb = base + (uint32_t)((c & 1) * 32768);
        if (c + 1 < NCH2) {
            uint32_t nb = base + (uint32_t)(((c + 1) & 1) * 32768);
            int k4 = (c + 1) * 4;
#pragma unroll
            for (int j = 0; j < 2; ++j) {
                size_t gA = (size_t)(m0 + lrow[j]) * (H_DIM / 8) + k4 + lg[j];
                size_t gB = (size_t)(n0 + lrow[j]) * (H_DIM / 8) + k4 + lg[j];
                CP_A16(nb + lsw[j],          (const void*)(pAH + gA));
                CP_A16(nb + 8192  + lsw[j],  (const void*)(pAL + gA));
                CP_A16(nb + 16384 + lsw[j],  (const void*)(pBH + gB));
                CP_A16(nb + 24576 + lsw[j],  (const void*)(pBL + gB));
            }
            CP_COMMIT();
            CP_WAIT(1);
        } else {
            CP_WAIT(0);
        }
        __syncthreads();
#pragma unroll
        for (int ks = 0; ks < 2; ++ks) {
            uint32_t bh0[4], bh1[4], bl0[4], bl1[4];
#pragma unroll
            for (int np = 0; np < 2; ++np) {
                uint32_t sw = SW64((uint32_t)((wn + np * 16 + lr) * 64 + ks * 32 + lk));
                uint32_t r0, r1, r2, r3;
                ldsm4(r0, r1, r2, r3, sb + 16384 + sw);
                bh0[np * 2] = r0; bh0[np * 2 + 1] = r1; bh1[np * 2] = r2; bh1[np * 2 + 1] = r3;
                ldsm4(r0, r1, r2, r3, sb + 24576 + sw);
                bl0[np * 2] = r0; bl0[np * 2 + 1] = r1; bl1[np * 2] = r2; bl1[np * 2 + 1] = r3;
            }
#pragma unroll
            for (int mt = 0; mt < 4; ++mt) {
                uint32_t sw = SW64((uint32_t)((wm + mt * 16 + lr) * 64 + ks * 32 + lk));
                uint32_t a_h[4], a_l[4];
                ldsm4(a_h[0], a_h[1], a_h[2], a_h[3], sb + sw);
                ldsm4(a_l[0], a_l[1], a_l[2], a_l[3], sb + 8192 + sw);
#pragma unroll
                for (int nt = 0; nt < 4; ++nt) {
                    mma16816(acc[mt][nt], a_h, bh0[nt], bh1[nt]);
                    mma16816(acc[mt][nt], a_h, bl0[nt], bl1[nt]);
                    mma16816(acc[mt][nt], a_l, bh0[nt], bh1[nt]);
                }
            }
        }
        __syncthreads();
    }

    // ---- fused epilogue straight from register accumulators ----
    float invL = g_scal[3], lam = g_scal[4];
    float bw0 = smw[20], bw1 = smw[21];
    float ca = 1.f + mom_next * (1.f - bw1);
    float cb = mom_next * bw0;
    int rbase = lane >> 2, cpair = (lane & 3) * 2;
#pragma unroll
    for (int mt = 0; mt < 4; ++mt) {
#pragma unroll
        for (int e2 = 0; e2 < 2; ++e2) {
            int m = m0 + wm + mt * 16 + rbase + e2 * 8;
            size_t rowoff = (size_t)m * H_DIM;
#pragma unroll
            for (int nt = 0; nt < 4; ++nt) {
                size_t idx = rowoff + n0 + wn + nt * 8 + cpair;
                float d0 = acc[mt][nt][e2 * 2 + 0];
                float d1 = acc[mt][nt][e2 * 2 + 1];
                __nv_bfloat162 h2 = *(const __nv_bfloat162*)&ah[idx];
                __nv_bfloat162 l2 = *(const __nv_bfloat162*)&al[idx];
                float2 u2 = *(const float2*)&g_u[idx];
                float za0 = __bfloat162float(h2.x) + __bfloat162float(l2.x);
                float za1 = __bfloat162float(h2.y) + __bfloat162float(l2.y);
                float zg0 = za0 - (d0 - u2.x) * invL;
                float zg1 = za1 - (d1 - u2.y) * invL;
                float zop0 = act_mix(zg0, smw, lam);
                float zop1 = act_mix(zg1, smw, lam);
                if (is_last) {
                    *(float2*)&outF[idx] = make_float2(zop0, zop1);
                } else {
                    float2 z2 = *(const float2*)&g_z[idx];
                    *(float2*)&g_z[idx] = make_float2(zop0, zop1);
                    float zan0 = ca * zop0 - cb * z2.x;
                    float zan1 = ca * zop1 - cb * z2.y;
                    __nv_bfloat162 ho, lo2;
                    ho.x = __float2bfloat16(zan0);
                    ho.y = __float2bfloat16(zan1);
                    lo2.x = __float2bfloat16(zan0 - __bfloat162float(ho.x));
                    lo2.y = __float2bfloat16(zan1 - __bfloat162float(ho.y));
                    *(__nv_bfloat162*)&aho[idx] = ho;
                    *(__nv_bfloat162*)&alo[idx] = lo2;
                }
            }
        }
    }
}

// ---------------- host orchestration (graph-capturable: kernel launches only) ----------------
extern "C" void kernel_launch(void* const* d_in, const int* in_sizes, int n_in,
                              void* d_out, int out_size) {
    const float* x     = (const float*)d_in[0];
    const float* W     = (const float*)d_in[1];
    const float* alpha = (const float*)d_in[2];
    const float* lbeta = (const float*)d_in[3];
    float* out = (float*)d_out;
    int T = in_sizes[2] / NOPS;
    if (T < 1) T = 1;
    if (T > 16) T = 16;

    const int DSM = 2 * 32768 + 1024;   // double-buffered stages + align slack
    cudaFuncSetAttribute(k_mma_iter, cudaFuncAttributeMaxDynamicSharedMemorySize, DSM);

    dim3 thr(256);

    // Spectral norm: A0 = WW^T (fp32 SIMT, split epilogue), 12 mma-squarings, finalize L
    k_wwT64<<<dim3(8, 8), thr>>>(W);
    for (int j = 0; j < PWRK; ++j)
        k_sqmma<<<dim3(8, 8), 128>>>(j & 1, j);
    k_finL<<<1, 512>>>();

    // One-time precomputes
    k_gemm_C<<<dim3(8, 8), thr>>>(W);
    k_splitC<<<(H_DIM * H_DIM) / 256, thr>>>();
    k_gemm_u<<<dim3(8, 32), thr>>>(x, W);
    k_weights<<<1, 32>>>(alpha, lbeta, T);

    // Iteration 0 (z = zprev = 0): elementwise
    k_iter0<<<(B_DIM * H_DIM) / (256 * 4), thr>>>((T == 1) ? out : nullptr);

    // Iterations 1..T-1: mma.sync fused GEMM + epilogue
    for (int i = 1; i < T; ++i) {
        float mom_next = (float)((double)(i + 1) / (double)(i + 4));
        int inSel  = (i + 1) & 1;
        int outSel = i & 1;
        int last = (i == T - 1);
        k_mma_iter<<<dim3(8, 32), thr, DSM>>>(inSel, outSel, last ? out : nullptr,
                                              i, mom_next, last);
    }
}

// round 15
// speedup vs baseline: 1.9935x; 1.0051x over previous
#include <cuda_runtime.h>
#include <cuda_bf16.h>
#include <math.h>
#include <stdint.h>

#define B_DIM 4096
#define N_DIM 512
#define H_DIM 1024
#define NOPS  20
#define PWRK  12               // squarings -> p = 2^12 = 4096
#define PINV  (1.0f/4096.0f)
#define KC2   32               // K chunk (bf16 cols) per stage, iteration GEMM
#define NCH2  (H_DIM / KC2)    // 32 chunks
#define NCTA_CHAIN 64

#define SW128(o) ((o) ^ (((o) >> 3) & 0x70))
#define SW64(o)  ((o) ^ (((o) >> 3) & 0x30))

// ---------------- static device scratch (no allocations allowed) ----------------
static __device__ float g_C[H_DIM * H_DIM];                                   // W^T W fp32
static __device__ __align__(16) __nv_bfloat16 g_Chi[H_DIM * H_DIM];           // C hi
static __device__ __align__(16) __nv_bfloat16 g_Clo[H_DIM * H_DIM];
static __device__ __align__(16) __nv_bfloat16 g_sAh[2][N_DIM * N_DIM];        // chain ping-pong hi
static __device__ __align__(16) __nv_bfloat16 g_sAl[2][N_DIM * N_DIM];        // chain ping-pong lo
static __device__ float g_u[(size_t)B_DIM * H_DIM];                           // W^T x
static __device__ float g_z[(size_t)B_DIM * H_DIM];                           // current z (fp32)
static __device__ __align__(16) __nv_bfloat16 g_ah[2][(size_t)B_DIM * H_DIM]; // z_aux hi ping-pong
static __device__ __align__(16) __nv_bfloat16 g_al[2][(size_t)B_DIM * H_DIM]; // z_aux lo ping-pong
static __device__ float g_scal[8];   // [3]=1/L, [4]=lam
static __device__ float g_w[16 * 24];
static __device__ int   g_bar;       // chain barrier counter (zeroed by k_wwT64 each replay)

// ---------------- PTX helpers (sm_80+ baseline: ldmatrix / mma.sync / cp.async) --------
__device__ __forceinline__ uint32_t smem_u32(const void* p) {
    uint32_t a;
    asm("{ .reg .u64 t; cvta.to.shared.u64 t, %1; cvt.u32.u64 %0, t; }" : "=r"(a) : "l"(p));
    return a;
}
__device__ __forceinline__ void ldsm4(uint32_t& r0, uint32_t& r1, uint32_t& r2, uint32_t& r3,
                                      uint32_t addr) {
    asm volatile("ldmatrix.sync.aligned.m8n8.x4.shared.b16 {%0,%1,%2,%3}, [%4];"
                 : "=r"(r0), "=r"(r1), "=r"(r2), "=r"(r3) : "r"(addr));
}
__device__ __forceinline__ void mma16816(float* d, const uint32_t* a, uint32_t b0, uint32_t b1) {
    asm volatile(
        "mma.sync.aligned.m16n8k16.row.col.f32.bf16.bf16.f32 "
        "{%0,%1,%2,%3}, {%4,%5,%6,%7}, {%8,%9}, {%0,%1,%2,%3};"
        : "+f"(d[0]), "+f"(d[1]), "+f"(d[2]), "+f"(d[3])
        : "r"(a[0]), "r"(a[1]), "r"(a[2]), "r"(a[3]), "r"(b0), "r"(b1));
}
#define CP_A16(dst, src) asm volatile("cp.async.cg.shared.global [%0], [%1], 16;" :: "r"(dst), "l"(src))
#define CP_COMMIT()      asm volatile("cp.async.commit_group;" ::: "memory")
#define CP_WAIT(n)       asm volatile("cp.async.wait_group %0;" :: "n"(n) : "memory")

// ---------------- 20-op activation mixture ----------------
__device__ __forceinline__ float act_mix(float v, const float* aw, float lam) {
    float av  = fabsf(v);
    float e   = expf(-av);
    float i1e = 1.0f / (1.0f + e);
    float sig = (v >= 0.f) ? i1e : e * i1e;
    float sp  = fmaxf(v, 0.f) + log1pf(e);
    float e2  = e * e;
    float tha = (1.f - e2) / (1.f + e2);
    float th  = (v >= 0.f) ? tha : -tha;
    float oms = 1.f - sig;
    float q   = oms * oms;
    float msh = (1.f - q) / (1.f + q);
    float erv = erff(v * 0.70710678118654752f);
    float em1 = e - 1.f;
    float elu = (v > 0.f) ? v : em1;
    float r6  = fminf(fmaxf(v + 3.f, 0.f), 6.f) * (1.f / 6.f);
    float r;
    r  = aw[0]  * ((v > lam) ? (v - lam) : ((v < -lam) ? (v + lam) : 0.f));
    r += aw[1]  * fmaxf(v, 0.f);
    r += aw[2]  * v;
    r += aw[3]  * (0.5f * v * (1.f + erv));
    r += aw[4]  * elu;
    r += aw[5]  * ((av > lam) ? v : 0.f);
    r += aw[6]  * fminf(fmaxf(v, -1.f), 1.f);
    r += aw[7]  * (v * r6);
    r += aw[8]  * (1.0507009873554805f * ((v > 0.f) ? v : 1.6732632423543772f * em1));
    r += aw[9]  * elu;
    r += aw[10] * ((v >= 0.f) ? v : 0.01f * v);
    r += aw[11] * (v - sp);
    r += aw[12] * (v - th);
    r += aw[13] * (v / (1.f + av));
    r += aw[14] * sp;
    r += aw[15] * th;
    r += aw[16] * sig;
    r += aw[17] * r6;
    r += aw[18] * (v * sig);
    r += aw[19] * (v * msh);
    return r;
}

// ---------------- A0 = W W^T [512x512], fp32 SIMT, epilogue emits bf16 hi/lo ----------------
__device__ __forceinline__ void ld64_T(float s[16][64], const float* src,
                                       int m0, int k0, int ld, int t) {
    int row = t >> 2, cv = (t & 3) * 4;
    float4 v = *(const float4*)&src[(size_t)(m0 + row) * ld + k0 + cv];
    s[cv + 0][row] = v.x; s[cv + 1][row] = v.y; s[cv + 2][row] = v.z; s[cv + 3][row] = v.w;
}
__device__ __forceinline__ void mma64(const float (*a)[64], const float (*b)[64],
                                      int tx, int ty, float acc[4][4]) {
#pragma unroll
    for (int kk = 0; kk < 16; ++kk) {
        float ar[4], br[4];
        *(float4*)ar = *(const float4*)&a[kk][ty * 4];
        *(float4*)br = *(const float4*)&b[kk][tx * 4];
#pragma unroll
        for (int i = 0; i < 4; ++i)
#pragma unroll
            for (int j = 0; j < 4; ++j)
                acc[i][j] = fmaf(ar[i], br[j], acc[i][j]);
    }
}
__global__ __launch_bounds__(256) void k_wwT64(const float* __restrict__ W) {
    __shared__ float a[16][64], b[16][64];
    int t = threadIdx.x, tx = t & 15, ty = t >> 4;
    int n0 = blockIdx.x * 64, m0 = blockIdx.y * 64;
    if (blockIdx.x == 0 && blockIdx.y == 0 && t == 0) g_bar = 0;   // reset chain barrier
    float acc[4][4] = {};
    for (int k0 = 0; k0 < H_DIM; k0 += 16) {
        ld64_T(a, W, m0, k0, H_DIM, t);
        ld64_T(b, W, n0, k0, H_DIM, t);
        __syncthreads();
        mma64(a, b, tx, ty, acc);
        __syncthreads();
    }
#pragma unroll
    for (int i = 0; i < 4; ++i)
#pragma unroll
        for (int j = 0; j < 4; ++j) {
            float v = acc[i][j];
            size_t o = (size_t)(m0 + ty * 4 + i) * N_DIM + n0 + tx * 4 + j;
            __nv_bfloat16 h = __float2bfloat16(v);
            g_sAh[0][o] = h;
            g_sAl[0][o] = __float2bfloat16(v - __bfloat162float(h));
        }
}

// ---------------- persistent spectral chain: 12 squarings + L, one kernel ----------------
// grid (8,8)=64 CTAs (co-resident), 128 threads. Body identical to R12's proven k_sqmma.
__global__ __launch_bounds__(128) void k_chain() {
    __shared__ __align__(16) char sm[32768];    // Ah 8K | Al 8K | Bh 8K | Bl 8K
    __shared__ float red[128];
    __shared__ float s_tr;
    int tid = threadIdx.x, wid = tid >> 5, lane = tid & 31;
    int m0 = blockIdx.y * 64, n0 = blockIdx.x * 64;
    int wm = (wid >> 1) * 32, wn = (wid & 1) * 32;
    int cta0 = (blockIdx.x == 0 && blockIdx.y == 0);
    uint32_t bAh = smem_u32(sm);
    int lr = lane & 15, lk = (lane >> 4) * 16;
    int rbase = lane >> 2, cpair = (lane & 3) * 2;
    float lnacc = 0.f;

    for (int j = 0; j < PWRK; ++j) {
        int src = j & 1;
        const __nv_bfloat16* Ah = g_sAh[src];
        const __nv_bfloat16* Al = g_sAl[src];
        __nv_bfloat16* Oh = g_sAh[src ^ 1];
        __nv_bfloat16* Ol = g_sAl[src ^ 1];
        // trace of input (hi+lo diag), redundant per CTA
        float ts = 0.f;
#pragma unroll
        for (int i = 0; i < 4; ++i) {
            int d = tid * 4 + i;
            ts += __bfloat162float(Ah[(size_t)d * (N_DIM + 1)]) +
                  __bfloat162float(Al[(size_t)d * (N_DIM + 1)]);
        }
        red[tid] = ts;
        __syncthreads();
        for (int s = 64; s > 0; s >>= 1) { if (tid < s) red[tid] += red[tid + s]; __syncthreads(); }
        if (tid == 0) s_tr = red[0];
        __syncthreads();
        float tr = s_tr;
        if (cta0 && tid == 0) lnacc += logf(tr) * ldexpf(1.f, -j);

        const uint4* pAh = (const uint4*)Ah;
        const uint4* pAl = (const uint4*)Al;
        float acc[2][4][4];
#pragma unroll
        for (int a = 0; a < 2; ++a)
#pragma unroll
            for (int b = 0; b < 4; ++b)
#pragma unroll
                for (int e = 0; e < 4; ++e) acc[a][b][e] = 0.f;

        for (int c = 0; c < 8; ++c) {               // K=512 in chunks of 64
            __syncthreads();
#pragma unroll
            for (int jj = 0; jj < 4; ++jj) {
                int s = tid + jj * 128;
                int row = s >> 3, g = s & 7;
                uint32_t sw = SW128((uint32_t)(row * 128 + g * 16));
                size_t gi = (size_t)(m0 + row) * 64 + c * 8 + g;
                size_t gj = (size_t)(n0 + row) * 64 + c * 8 + g;
                *(uint4*)(sm + sw)         = pAh[gi];
                *(uint4*)(sm + 8192 + sw)  = pAl[gi];
                *(uint4*)(sm + 16384 + sw) = pAh[gj];
                *(uint4*)(sm + 24576 + sw) = pAl[gj];
            }
            __syncthreads();
#pragma unroll
            for (int ks = 0; ks < 4; ++ks) {
                uint32_t bh0[4], bh1[4], bl0[4], bl1[4];
#pragma unroll
                for (int np = 0; np < 2; ++np) {
                    uint32_t sw = SW128((uint32_t)((wn + np * 16 + lr) * 128 + ks * 32 + lk));
                    uint32_t r0, r1, r2, r3;
                    ldsm4(r0, r1, r2, r3, bAh + 16384 + sw);
                    bh0[np * 2] = r0; bh0[np * 2 + 1] = r1; bh1[np * 2] = r2; bh1[np * 2 + 1] = r3;
                    ldsm4(r0, r1, r2, r3, bAh + 24576 + sw);
                    bl0[np * 2] = r0; bl0[np * 2 + 1] = r1; bl1[np * 2] = r2; bl1[np * 2 + 1] = r3;
                }
#pragma unroll
                for (int mt = 0; mt < 2; ++mt) {
                    uint32_t sw = SW128((uint32_t)((wm + mt * 16 + lr) * 128 + ks * 32 + lk));
                    uint32_t a_h[4], a_l[4];
                    ldsm4(a_h[0], a_h[1], a_h[2], a_h[3], bAh + sw);
                    ldsm4(a_l[0], a_l[1], a_l[2], a_l[3], bAh + 8192 + sw);
#pragma unroll
                    for (int nt = 0; nt < 4; ++nt) {
                        mma16816(acc[mt][nt], a_h, bh0[nt], bh1[nt]);
                        mma16816(acc[mt][nt], a_h, bl0[nt], bl1[nt]);
                        mma16816(acc[mt][nt], a_l, bh0[nt], bh1[nt]);
                        mma16816(acc[mt][nt], a_l, bl0[nt], bl1[nt]);
                    }
                }
            }
        }
        float sc = 1.f / (tr * tr);
#pragma unroll
        for (int mt = 0; mt < 2; ++mt)
#pragma unroll
            for (int e2 = 0; e2 < 2; ++e2) {
                int m = m0 + wm + mt * 16 + rbase + e2 * 8;
#pragma unroll
                for (int nt = 0; nt < 4; ++nt) {
                    size_t idx = (size_t)m * N_DIM + n0 + wn + nt * 8 + cpair;
                    float v0 = acc[mt][nt][e2 * 2 + 0] * sc;
                    float v1 = acc[mt][nt][e2 * 2 + 1] * sc;
                    __nv_bfloat162 h2, l2;
                    h2.x = __float2bfloat16(v0); h2.y = __float2bfloat16(v1);
                    l2.x = __float2bfloat16(v0 - __bfloat162float(h2.x));
                    l2.y = __float2bfloat16(v1 - __bfloat162float(h2.y));
                    *(__nv_bfloat162*)&Oh[idx] = h2;
                    *(__nv_bfloat162*)&Ol[idx] = l2;
                }
            }
        // software global barrier between squarings (64 co-resident CTAs)
        __syncthreads();
        if (tid == 0) {
            __threadfence();
            atomicAdd(&g_bar, 1);
            int target = NCTA_CHAIN * (j + 1);
            while (atomicAdd(&g_bar, 0) < target) __nanosleep(64);
        }
        __syncthreads();
    }
    // finalize L (final matrix in buffer 0 since PWRK even)
    if (cta0) {
        float ts = 0.f;
#pragma unroll
        for (int i = 0; i < 4; ++i) {
            int d = tid * 4 + i;
            ts += __bfloat162float(g_sAh[0][(size_t)d * (N_DIM + 1)]) +
                  __bfloat162float(g_sAl[0][(size_t)d * (N_DIM + 1)]);
        }
        red[tid] = ts;
        __syncthreads();
        for (int s = 64; s > 0; s >>= 1) { if (tid < s) red[tid] += red[tid + s]; __syncthreads(); }
        if (tid == 0) {
            float lnL = lnacc + logf(red[0]) * PINV;
            float L = expf(lnL);
            g_scal[3] = 1.f / L;
            g_scal[4] = 0.001f / L;
        }
    }
}

// ---------------- 128x128 SIMT fp32 GEMMs (C and u, one-time; proven R12 kernels) ------
__device__ __forceinline__ void load_A_T(float s[16][128], const float* src,
                                         int m0, int k0, int ld, int t) {
#pragma unroll
    for (int l = 0; l < 2; ++l) {
        int fid = t + l * 256;
        int row = fid >> 2, cv = (fid & 3) * 4;
        float4 v = *(const float4*)&src[(size_t)(m0 + row) * ld + k0 + cv];
        s[cv + 0][row] = v.x; s[cv + 1][row] = v.y;
        s[cv + 2][row] = v.z; s[cv + 3][row] = v.w;
    }
}
__device__ __forceinline__ void load_B_N(float s[16][128], const float* src,
                                         int k0, int n0, int ld, int t) {
#pragma unroll
    for (int l = 0; l < 2; ++l) {
        int fid = t + l * 256;
        int row = fid >> 5, cv = (fid & 31) * 4;
        *(float4*)&s[row][cv] = *(const float4*)&src[(size_t)(k0 + row) * ld + n0 + cv];
    }
}
__device__ __forceinline__ void mma_chunk(const float (*a_s)[128], const float (*b_s)[128],
                                          int tx, int ty, float acc[8][8]) {
#pragma unroll
    for (int kk = 0; kk < 16; ++kk) {
        float ar[8], br[8];
        *(float4*)&ar[0] = *(const float4*)&a_s[kk][ty * 8];
        *(float4*)&ar[4] = *(const float4*)&a_s[kk][ty * 8 + 4];
        *(float4*)&br[0] = *(const float4*)&b_s[kk][tx * 8];
        *(float4*)&br[4] = *(const float4*)&b_s[kk][tx * 8 + 4];
#pragma unroll
        for (int i = 0; i < 8; ++i)
#pragma unroll
            for (int j = 0; j < 8; ++j)
                acc[i][j] = fmaf(ar[i], br[j], acc[i][j]);
    }
}
__device__ __forceinline__ void store_tile(float* outp, int ldo, int m0, int n0,
                                           int tx, int ty, const float acc[8][8]) {
#pragma unroll
    for (int i = 0; i < 8; ++i) {
        size_t off = (size_t)(m0 + ty * 8 + i) * ldo + n0 + tx * 8;
        *(float4*)&outp[off]     = make_float4(acc[i][0], acc[i][1], acc[i][2], acc[i][3]);
        *(float4*)&outp[off + 4] = make_float4(acc[i][4], acc[i][5], acc[i][6], acc[i][7]);
    }
}
__global__ __launch_bounds__(256) void k_gemm_C(const float* __restrict__ W) {
    __shared__ float a_s[16][128], b_s[16][128];
    int t = threadIdx.x, tx = t & 15, ty = t >> 4;
    int n0 = blockIdx.x * 128, m0 = blockIdx.y * 128;
    float acc[8][8] = {};
    for (int k0 = 0; k0 < N_DIM; k0 += 16) {
        load_B_N(a_s, W, k0, m0, H_DIM, t);
        load_B_N(b_s, W, k0, n0, H_DIM, t);
        __syncthreads();
        mma_chunk(a_s, b_s, tx, ty, acc);
        __syncthreads();
    }
    store_tile(g_C, H_DIM, m0, n0, tx, ty, acc);
}
__global__ __launch_bounds__(256) void k_gemm_u(const float* __restrict__ x,
                                                const float* __restrict__ W) {
    __shared__ float a_s[16][128], b_s[16][128];
    int t = threadIdx.x, tx = t & 15, ty = t >> 4;
    int n0 = blockIdx.x * 128, m0 = blockIdx.y * 128;
    float acc[8][8] = {};
    for (int k0 = 0; k0 < N_DIM; k0 += 16) {
        load_A_T(a_s, x, m0, k0, N_DIM, t);
        load_B_N(b_s, W, k0, n0, H_DIM, t);
        __syncthreads();
        mma_chunk(a_s, b_s, tx, ty, acc);
        __syncthreads();
    }
    store_tile(g_u, H_DIM, m0, n0, tx, ty, acc);
}
__global__ void k_splitC() {
    int idx = blockIdx.x * 256 + threadIdx.x;
    float v = g_C[idx];
    __nv_bfloat16 h = __float2bfloat16(v);
    g_Chi[idx] = h;
    g_Clo[idx] = __float2bfloat16(v - __bfloat162float(h));
}
__global__ void k_weights(const float* __restrict__ alpha, const float* __restrict__ beta, int T) {
    int i = threadIdx.x;
    if (i >= T) return;
    float m = -1e30f;
    for (int k = 0; k < NOPS; ++k) m = fmaxf(m, alpha[i * NOPS + k]);
    float e[NOPS], s = 0.f;
    for (int k = 0; k < NOPS; ++k) { e[k] = expf(alpha[i * NOPS + k] - m); s += e[k]; }
    float invs = 1.f / s;
    for (int k = 0; k < NOPS; ++k) g_w[i * 24 + k] = e[k] * invs;
    float b0 = beta[i * 2], b1 = beta[i * 2 + 1];
    float mb = fmaxf(b0, b1);
    float e0 = expf(b0 - mb), e1 = expf(b1 - mb);
    float ib = 1.f / (e0 + e1);
    g_w[i * 24 + 20] = e0 * ib;
    g_w[i * 24 + 21] = e1 * ib;
}
// iteration 0: z_g = u/L elementwise; emits z and z_aux(hi/lo) for iter 1
__global__ void k_iter0(float* outF) {
    __shared__ float smw[24];
    int t = threadIdx.x;
    if (t < 22) smw[t] = g_w[t];
    __syncthreads();
    float invL = g_scal[3], lam = g_scal[4];
    float bw1 = smw[21];
    float mom1 = 0.25f;
    float ca = 1.f + mom1 * (1.f - bw1);
    size_t idx = ((size_t)blockIdx.x * 256 + t) * 4;
    float4 uu = *(const float4*)&g_u[idx];
    float zo[4];
    zo[0] = act_mix(uu.x * invL, smw, lam);
    zo[1] = act_mix(uu.y * invL, smw, lam);
    zo[2] = act_mix(uu.z * invL, smw, lam);
    zo[3] = act_mix(uu.w * invL, smw, lam);
    if (outF) {
        *(float4*)&outF[idx] = make_float4(zo[0], zo[1], zo[2], zo[3]);
    } else {
        *(float4*)&g_z[idx] = make_float4(zo[0], zo[1], zo[2], zo[3]);
#pragma unroll
        for (int j = 0; j < 4; ++j) {
            float za = ca * zo[j];
            __nv_bfloat16 h = __float2bfloat16(za);
            g_ah[0][idx + j] = h;
            g_al[0][idx + j] = __float2bfloat16(za - __bfloat162float(h));
        }
    }
}

// ---------------- iteration: split-3 mma + fused epilogue, 2-stage cp.async (R12 proven) ----
__global__ __launch_bounds__(256, 2) void k_mma_iter(int inSel, int outSel, float* outF,
                                                     int iter, float mom_next, int is_last) {
    extern __shared__ char dsm[];
    __shared__ float smw[24];

    const __nv_bfloat16* __restrict__ ah = g_ah[inSel];
    const __nv_bfloat16* __restrict__ al = g_al[inSel];
    __nv_bfloat16* __restrict__ aho = g_ah[outSel];
    __nv_bfloat16* __restrict__ alo = g_al[outSel];

    int tid = threadIdx.x, wid = tid >> 5, lane = tid & 31;
    int m0 = blockIdx.y * 128, n0 = blockIdx.x * 128;
    int wm = (wid >> 2) * 64, wn = (wid & 3) * 32;

    char* tp = (char*)(((uintptr_t)dsm + 1023) & ~(uintptr_t)1023);
    uint32_t base = smem_u32(tp);
    if (tid < 22) smw[tid] = g_w[iter * 24 + tid];

    const uint4* pAH = (const uint4*)ah;
    const uint4* pAL = (const uint4*)al;
    const uint4* pBH = (const uint4*)g_Chi;
    const uint4* pBL = (const uint4*)g_Clo;

    float acc[4][4][4];
#pragma unroll
    for (int a = 0; a < 4; ++a)
#pragma unroll
        for (int b = 0; b < 4; ++b)
#pragma unroll
            for (int e = 0; e < 4; ++e) acc[a][b][e] = 0.f;

    int lrow[2], lg[2];
    uint32_t lsw[2];
#pragma unroll
    for (int j = 0; j < 2; ++j) {
        int s = tid + j * 256;
        lrow[j] = s >> 2; lg[j] = s & 3;
        lsw[j] = SW64((uint32_t)(lrow[j] * 64 + lg[j] * 16));
    }
    int lr = lane & 15, lk = (lane >> 4) * 16;

    // prologue: chunk 0 into stage 0
#pragma unroll
    for (int j = 0; j < 2; ++j) {
        size_t gA = (size_t)(m0 + lrow[j]) * (H_DIM / 8) + lg[j];
        size_t gB = (size_t)(n0 + lrow[j]) * (H_DIM / 8) + lg[j];
        CP_A16(base + lsw[j],          (const void*)(pAH + gA));
        CP_A16(base + 8192  + lsw[j],  (const void*)(pAL + gA));
        CP_A16(base + 16384 + lsw[j],  (const void*)(pBH + gB));
        CP_A16(base + 24576 + lsw[j],  (const void*)(pBL + gB));
    }
    CP_COMMIT();

    for (int c = 0; c < NCH2; ++c) {
        uint32_t sb = base + (uint32_t)((c & 1) * 32768);
        if (c + 1 < NCH2) {
            uint32_t nb = base + (uint32_t)(((c + 1) & 1) * 32768);
            int k4 = (c + 1) * 4;
#pragma unroll
            for (int j = 0; j < 2; ++j) {
                size_t gA = (size_t)(m0 + lrow[j]) * (H_DIM / 8) + k4 + lg[j];
                size_t gB = (size_t)(n0 + lrow[j]) * (H_DIM / 8) + k4 + lg[j];
                CP_A16(nb + lsw[j],          (const void*)(pAH + gA));
                CP_A16(nb + 8192  + lsw[j],  (const void*)(pAL + gA));
                CP_A16(nb + 16384 + lsw[j],  (const void*)(pBH + gB));
                CP_A16(nb + 24576 + lsw[j],  (const void*)(pBL + gB));
            }
            CP_COMMIT();
            CP_WAIT(1);
        } else {
            CP_WAIT(0);
        }
        __syncthreads();
#pragma unroll
        for (int ks = 0; ks < 2; ++ks) {
            uint32_t bh0[4], bh1[4], bl0[4], bl1[4];
#pragma unroll
            for (int np = 0; np < 2; ++np) {
                uint32_t sw = SW64((uint32_t)((wn + np * 16 + lr) * 64 + ks * 32 + lk));
                uint32_t r0, r1, r2, r3;
                ldsm4(r0, r1, r2, r3, sb + 16384 + sw);
                bh0[np * 2] = r0; bh0[np * 2 + 1] = r1; bh1[np * 2] = r2; bh1[np * 2 + 1] = r3;
                ldsm4(r0, r1, r2, r3, sb + 24576 + sw);
                bl0[np * 2] = r0; bl0[np * 2 + 1] = r1; bl1[np * 2] = r2; bl1[np * 2 + 1] = r3;
            }
#pragma unroll
            for (int mt = 0; mt < 4; ++mt) {
                uint32_t sw = SW64((uint32_t)((wm + mt * 16 + lr) * 64 + ks * 32 + lk));
                uint32_t a_h[4], a_l[4];
                ldsm4(a_h[0], a_h[1], a_h[2], a_h[3], sb + sw);
                ldsm4(a_l[0], a_l[1], a_l[2], a_l[3], sb + 8192 + sw);
#pragma unroll
                for (int nt = 0; nt < 4; ++nt) {
                    mma16816(acc[mt][nt], a_h, bh0[nt], bh1[nt]);
                    mma16816(acc[mt][nt], a_h, bl0[nt], bl1[nt]);
                    mma16816(acc[mt][nt], a_l, bh0[nt], bh1[nt]);
                }
            }
        }
        __syncthreads();
    }

    // ---- fused epilogue straight from register accumulators ----
    float invL = g_scal[3], lam = g_scal[4];
    float bw0 = smw[20], bw1 = smw[21];
    float ca = 1.f + mom_next * (1.f - bw1);
    float cb = mom_next * bw0;
    int rbase = lane >> 2, cpair = (lane & 3) * 2;
#pragma unroll
    for (int mt = 0; mt < 4; ++mt) {
#pragma unroll
        for (int e2 = 0; e2 < 2; ++e2) {
            int m = m0 + wm + mt * 16 + rbase + e2 * 8;
            size_t rowoff = (size_t)m * H_DIM;
#pragma unroll
            for (int nt = 0; nt < 4; ++nt) {
                size_t idx = rowoff + n0 + wn + nt * 8 + cpair;
                float d0 = acc[mt][nt][e2 * 2 + 0];
                float d1 = acc[mt][nt][e2 * 2 + 1];
                __nv_bfloat162 h2 = *(const __nv_bfloat162*)&ah[idx];
                __nv_bfloat162 l2 = *(const __nv_bfloat162*)&al[idx];
                float2 u2 = *(const float2*)&g_u[idx];
                float za0 = __bfloat162float(h2.x) + __bfloat162float(l2.x);
                float za1 = __bfloat162float(h2.y) + __bfloat162float(l2.y);
                float zg0 = za0 - (d0 - u2.x) * invL;
                float zg1 = za1 - (d1 - u2.y) * invL;
                float zop0 = act_mix(zg0, smw, lam);
                float zop1 = act_mix(zg1, smw, lam);
                if (is_last) {
                    *(float2*)&outF[idx] = make_float2(zop0, zop1);
                } else {
                    float2 z2 = *(const float2*)&g_z[idx];
                    *(float2*)&g_z[idx] = make_float2(zop0, zop1);
                    float zan0 = ca * zop0 - cb * z2.x;
                    float zan1 = ca * zop1 - cb * z2.y;
                    __nv_bfloat162 ho, lo2;
                    ho.x = __float2bfloat16(zan0);
                    ho.y = __float2bfloat16(zan1);
                    lo2.x = __float2bfloat16(zan0 - __bfloat162float(ho.x));
                    lo2.y = __float2bfloat16(zan1 - __bfloat162float(ho.y));
                    *(__nv_bfloat162*)&aho[idx] = ho;
                    *(__nv_bfloat162*)&alo[idx] = lo2;
                }
            }
        }
    }
}

// ---------------- host orchestration (graph-capturable: kernel launches only) ----------------
extern "C" void kernel_launch(void* const* d_in, const int* in_sizes, int n_in,
                              void* d_out, int out_size) {
    const float* x     = (const float*)d_in[0];
    const float* W     = (const float*)d_in[1];
    const float* alpha = (const float*)d_in[2];
    const float* lbeta = (const float*)d_in[3];
    float* out = (float*)d_out;
    int T = in_sizes[2] / NOPS;
    if (T < 1) T = 1;
    if (T > 16) T = 16;

    const int DSM = 2 * 32768 + 1024;   // double-buffered stages + align slack
    cudaFuncSetAttribute(k_mma_iter, cudaFuncAttributeMaxDynamicSharedMemorySize, DSM);

    dim3 thr(256);

    // Spectral norm: A0 = WW^T (fp32 SIMT, split epilogue + barrier reset),
    // then ONE persistent kernel for 12 squarings + L finalize.
    k_wwT64<<<dim3(8, 8), thr>>>(W);
    k_chain<<<dim3(8, 8), 128>>>();

    // One-time precomputes (proven R12 fp32 SIMT kernels)
    k_gemm_C<<<dim3(8, 8), thr>>>(W);
    k_splitC<<<(H_DIM * H_DIM) / 256, thr>>>();
    k_gemm_u<<<dim3(8, 32), thr>>>(x, W);
    k_weights<<<1, 32>>>(alpha, lbeta, T);

    // Iteration 0 (z = zprev = 0): elementwise
    k_iter0<<<(B_DIM * H_DIM) / (256 * 4), thr>>>((T == 1) ? out : nullptr);

    // Iterations 1..T-1: mma.sync fused GEMM + epilogue
    for (int i = 1; i < T; ++i) {
        float mom_next = (float)((double)(i + 1) / (double)(i + 4));
        int inSel  = (i + 1) & 1;
        int outSel = i & 1;
        int last = (i == T - 1);
        k_mma_iter<<<dim3(8, 32), thr, DSM>>>(inSel, outSel, last ? out : nullptr,
                                              i, mom_next, last);
    }
}

// round 16
// speedup vs baseline: 2.1787x; 1.0929x over previous
#include <cuda_runtime.h>
#include <cuda_bf16.h>
#include <math.h>
#include <stdint.h>

#define B_DIM 4096
#define N_DIM 512
#define H_DIM 1024
#define NOPS  20
#define PWRK  10               // squarings -> p = 2^10 = 1024 (TW gap -> e^-16 converged)
#define PINV  (1.0f/1024.0f)
#define KC2   32               // K chunk (bf16 cols) per stage
#define NCH2  (H_DIM / KC2)    // 32 chunks (iteration GEMM)
#define NCHU  (N_DIM / KC2)    // 16 chunks (u / C GEMMs)
#define NCTA_CHAIN 64

#define SW128(o) ((o) ^ (((o) >> 3) & 0x70))
#define SW64(o)  ((o) ^ (((o) >> 3) & 0x30))

// ---------------- static device scratch (no allocations allowed) ----------------
static __device__ __align__(16) __nv_bfloat16 g_Wthi[H_DIM * N_DIM];          // W^T hi
static __device__ __align__(16) __nv_bfloat16 g_Wtlo[H_DIM * N_DIM];          // W^T lo
static __device__ __align__(16) __nv_bfloat16 g_xh[(size_t)B_DIM * N_DIM];    // x hi
static __device__ __align__(16) __nv_bfloat16 g_xl[(size_t)B_DIM * N_DIM];    // x lo
static __device__ __align__(16) __nv_bfloat16 g_Chi[H_DIM * H_DIM];           // C hi
static __device__ __align__(16) __nv_bfloat16 g_Clo[H_DIM * H_DIM];           // C lo
static __device__ __align__(16) __nv_bfloat16 g_sAh[2][N_DIM * N_DIM];        // chain ping-pong hi
static __device__ __align__(16) __nv_bfloat16 g_sAl[2][N_DIM * N_DIM];        // chain ping-pong lo
static __device__ float g_u[(size_t)B_DIM * H_DIM];                           // W^T x
static __device__ float g_z[(size_t)B_DIM * H_DIM];                           // current z (fp32)
static __device__ __align__(16) __nv_bfloat16 g_ah[2][(size_t)B_DIM * H_DIM]; // z_aux hi ping-pong
static __device__ __align__(16) __nv_bfloat16 g_al[2][(size_t)B_DIM * H_DIM]; // z_aux lo ping-pong
static __device__ float g_scal[8];   // [3]=1/L, [4]=lam
static __device__ float g_w[16 * 24];
static __device__ int   g_bar;       // chain barrier counter (zeroed by k_wwT64 each replay)

// ---------------- PTX helpers (sm_80+ baseline: ldmatrix / mma.sync / cp.async) --------
__device__ __forceinline__ uint32_t smem_u32(const void* p) {
    uint32_t a;
    asm("{ .reg .u64 t; cvta.to.shared.u64 t, %1; cvt.u32.u64 %0, t; }" : "=r"(a) : "l"(p));
    return a;
}
__device__ __forceinline__ void ldsm4(uint32_t& r0, uint32_t& r1, uint32_t& r2, uint32_t& r3,
                                      uint32_t addr) {
    asm volatile("ldmatrix.sync.aligned.m8n8.x4.shared.b16 {%0,%1,%2,%3}, [%4];"
                 : "=r"(r0), "=r"(r1), "=r"(r2), "=r"(r3) : "r"(addr));
}
__device__ __forceinline__ void mma16816(float* d, const uint32_t* a, uint32_t b0, uint32_t b1) {
    asm volatile(
        "mma.sync.aligned.m16n8k16.row.col.f32.bf16.bf16.f32 "
        "{%0,%1,%2,%3}, {%4,%5,%6,%7}, {%8,%9}, {%0,%1,%2,%3};"
        : "+f"(d[0]), "+f"(d[1]), "+f"(d[2]), "+f"(d[3])
        : "r"(a[0]), "r"(a[1]), "r"(a[2]), "r"(a[3]), "r"(b0), "r"(b1));
}
#define CP_A16(dst, src) asm volatile("cp.async.cg.shared.global [%0], [%1], 16;" :: "r"(dst), "l"(src))
#define CP_COMMIT()      asm volatile("cp.async.commit_group;" ::: "memory")
#define CP_WAIT(n)       asm volatile("cp.async.wait_group %0;" :: "n"(n) : "memory")

// ---------------- 20-op activation mixture ----------------
__device__ __forceinline__ float act_mix(float v, const float* aw, float lam) {
    float av  = fabsf(v);
    float e   = expf(-av);
    float i1e = 1.0f / (1.0f + e);
    float sig = (v >= 0.f) ? i1e : e * i1e;
    float sp  = fmaxf(v, 0.f) + log1pf(e);
    float e2  = e * e;
    float tha = (1.f - e2) / (1.f + e2);
    float th  = (v >= 0.f) ? tha : -tha;
    float oms = 1.f - sig;
    float q   = oms * oms;
    float msh = (1.f - q) / (1.f + q);
    float erv = erff(v * 0.70710678118654752f);
    float em1 = e - 1.f;
    float elu = (v > 0.f) ? v : em1;
    float r6  = fminf(fmaxf(v + 3.f, 0.f), 6.f) * (1.f / 6.f);
    float r;
    r  = aw[0]  * ((v > lam) ? (v - lam) : ((v < -lam) ? (v + lam) : 0.f));
    r += aw[1]  * fmaxf(v, 0.f);
    r += aw[2]  * v;
    r += aw[3]  * (0.5f * v * (1.f + erv));
    r += aw[4]  * elu;
    r += aw[5]  * ((av > lam) ? v : 0.f);
    r += aw[6]  * fminf(fmaxf(v, -1.f), 1.f);
    r += aw[7]  * (v * r6);
    r += aw[8]  * (1.0507009873554805f * ((v > 0.f) ? v : 1.6732632423543772f * em1));
    r += aw[9]  * elu;
    r += aw[10] * ((v >= 0.f) ? v : 0.01f * v);
    r += aw[11] * (v - sp);
    r += aw[12] * (v - th);
    r += aw[13] * (v / (1.f + av));
    r += aw[14] * sp;
    r += aw[15] * th;
    r += aw[16] * sig;
    r += aw[17] * r6;
    r += aw[18] * (v * sig);
    r += aw[19] * (v * msh);
    return r;
}

// ---------------- A0 = W W^T [512x512], fp32 SIMT, epilogue emits bf16 hi/lo ----------------
__device__ __forceinline__ void ld64_T(float s[16][64], const float* src,
                                       int m0, int k0, int ld, int t) {
    int row = t >> 2, cv = (t & 3) * 4;
    float4 v = *(const float4*)&src[(size_t)(m0 + row) * ld + k0 + cv];
    s[cv + 0][row] = v.x; s[cv + 1][row] = v.y; s[cv + 2][row] = v.z; s[cv + 3][row] = v.w;
}
__device__ __forceinline__ void mma64(const float (*a)[64], const float (*b)[64],
                                      int tx, int ty, float acc[4][4]) {
#pragma unroll
    for (int kk = 0; kk < 16; ++kk) {
        float ar[4], br[4];
        *(float4*)ar = *(const float4*)&a[kk][ty * 4];
        *(float4*)br = *(const float4*)&b[kk][tx * 4];
#pragma unroll
        for (int i = 0; i < 4; ++i)
#pragma unroll
            for (int j = 0; j < 4; ++j)
                acc[i][j] = fmaf(ar[i], br[j], acc[i][j]);
    }
}
__global__ __launch_bounds__(256) void k_wwT64(const float* __restrict__ W) {
    __shared__ float a[16][64], b[16][64];
    int t = threadIdx.x, tx = t & 15, ty = t >> 4;
    int n0 = blockIdx.x * 64, m0 = blockIdx.y * 64;
    if (blockIdx.x == 0 && blockIdx.y == 0 && t == 0) g_bar = 0;   // reset chain barrier
    float acc[4][4] = {};
    for (int k0 = 0; k0 < H_DIM; k0 += 16) {
        ld64_T(a, W, m0, k0, H_DIM, t);
        ld64_T(b, W, n0, k0, H_DIM, t);
        __syncthreads();
        mma64(a, b, tx, ty, acc);
        __syncthreads();
    }
#pragma unroll
    for (int i = 0; i < 4; ++i)
#pragma unroll
        for (int j = 0; j < 4; ++j) {
            float v = acc[i][j];
            size_t o = (size_t)(m0 + ty * 4 + i) * N_DIM + n0 + tx * 4 + j;
            __nv_bfloat16 h = __float2bfloat16(v);
            g_sAh[0][o] = h;
            g_sAl[0][o] = __float2bfloat16(v - __bfloat162float(h));
        }
}

// ---------------- persistent spectral chain: 10 squarings + L, one kernel ----------------
// grid (8,8)=64 CTAs (co-resident), 256 threads (8 warps, warp tile 16x32).
__global__ __launch_bounds__(256) void k_chain() {
    __shared__ __align__(16) char sm[32768];    // Ah 8K | Al 8K | Bh 8K | Bl 8K
    __shared__ float red[256];
    __shared__ float s_tr;
    int tid = threadIdx.x, wid = tid >> 5, lane = tid & 31;
    int m0 = blockIdx.y * 64, n0 = blockIdx.x * 64;
    int wm = (wid & 3) * 16, wn = (wid >> 2) * 32;   // 4x2 warp grid, tile 16x32
    int cta0 = (blockIdx.x == 0 && blockIdx.y == 0);
    uint32_t bAh = smem_u32(sm);
    int lr = lane & 15, lk = (lane >> 4) * 16;
    int rbase = lane >> 2, cpair = (lane & 3) * 2;
    float lnacc = 0.f;

    for (int j = 0; j < PWRK; ++j) {
        int src = j & 1;
        const __nv_bfloat16* Ah = g_sAh[src];
        const __nv_bfloat16* Al = g_sAl[src];
        __nv_bfloat16* Oh = g_sAh[src ^ 1];
        __nv_bfloat16* Ol = g_sAl[src ^ 1];
        // trace of input (hi+lo diag), redundant per CTA
        float ts = 0.f;
#pragma unroll
        for (int i = 0; i < 2; ++i) {
            int d = tid * 2 + i;
            ts += __bfloat162float(Ah[(size_t)d * (N_DIM + 1)]) +
                  __bfloat162float(Al[(size_t)d * (N_DIM + 1)]);
        }
        red[tid] = ts;
        __syncthreads();
        for (int s = 128; s > 0; s >>= 1) { if (tid < s) red[tid] += red[tid + s]; __syncthreads(); }
        if (tid == 0) s_tr = red[0];
        __syncthreads();
        float tr = s_tr;
        if (cta0 && tid == 0) lnacc += logf(tr) * ldexpf(1.f, -j);

        const uint4* pAh = (const uint4*)Ah;
        const uint4* pAl = (const uint4*)Al;
        float acc[4][4];                 // [nt][4] for the 16x32 warp tile
#pragma unroll
        for (int b = 0; b < 4; ++b)
#pragma unroll
            for (int e = 0; e < 4; ++e) acc[b][e] = 0.f;

        for (int c = 0; c < 8; ++c) {               // K=512 in chunks of 64
            __syncthreads();
#pragma unroll
            for (int jj = 0; jj < 2; ++jj) {        // 2 granules per thread per tensor
                int s = tid + jj * 256;
                int row = s >> 3, g = s & 7;
                uint32_t sw = SW128((uint32_t)(row * 128 + g * 16));
                size_t gi = (size_t)(m0 + row) * 64 + c * 8 + g;
                size_t gj = (size_t)(n0 + row) * 64 + c * 8 + g;
                *(uint4*)(sm + sw)         = pAh[gi];
                *(uint4*)(sm + 8192 + sw)  = pAl[gi];
                *(uint4*)(sm + 16384 + sw) = pAh[gj];
                *(uint4*)(sm + 24576 + sw) = pAl[gj];
            }
            __syncthreads();
#pragma unroll
            for (int ks = 0; ks < 4; ++ks) {
                uint32_t bh0[4], bh1[4], bl0[4], bl1[4];
#pragma unroll
                for (int np = 0; np < 2; ++np) {
                    uint32_t sw = SW128((uint32_t)((wn + np * 16 + lr) * 128 + ks * 32 + lk));
                    uint32_t r0, r1, r2, r3;
                    ldsm4(r0, r1, r2, r3, bAh + 16384 + sw);
                    bh0[np * 2] = r0; bh0[np * 2 + 1] = r1; bh1[np * 2] = r2; bh1[np * 2 + 1] = r3;
                    ldsm4(r0, r1, r2, r3, bAh + 24576 + sw);
                    bl0[np * 2] = r0; bl0[np * 2 + 1] = r1; bl1[np * 2] = r2; bl1[np * 2 + 1] = r3;
                }
                uint32_t sw = SW128((uint32_t)((wm + lr) * 128 + ks * 32 + lk));
                uint32_t a_h[4], a_l[4];
                ldsm4(a_h[0], a_h[1], a_h[2], a_h[3], bAh + sw);
                ldsm4(a_l[0], a_l[1], a_l[2], a_l[3], bAh + 8192 + sw);
#pragma unroll
                for (int nt = 0; nt < 4; ++nt) {
                    mma16816(acc[nt], a_h, bh0[nt], bh1[nt]);
                    mma16816(acc[nt], a_h, bl0[nt], bl1[nt]);
                    mma16816(acc[nt], a_l, bh0[nt], bh1[nt]);
                    mma16816(acc[nt], a_l, bl0[nt], bl1[nt]);   // split-4 chain accuracy
                }
            }
        }
        float sc = 1.f / (tr * tr);
#pragma unroll
        for (int e2 = 0; e2 < 2; ++e2) {
            int m = m0 + wm + rbase + e2 * 8;
#pragma unroll
            for (int nt = 0; nt < 4; ++nt) {
                size_t idx = (size_t)m * N_DIM + n0 + wn + nt * 8 + cpair;
                float v0 = acc[nt][e2 * 2 + 0] * sc;
                float v1 = acc[nt][e2 * 2 + 1] * sc;
                __nv_bfloat162 h2, l2;
                h2.x = __float2bfloat16(v0); h2.y = __float2bfloat16(v1);
                l2.x = __float2bfloat16(v0 - __bfloat162float(h2.x));
                l2.y = __float2bfloat16(v1 - __bfloat162float(h2.y));
                *(__nv_bfloat162*)&Oh[idx] = h2;
                *(__nv_bfloat162*)&Ol[idx] = l2;
            }
        }
        // software global barrier between squarings (64 co-resident CTAs)
        __syncthreads();
        if (tid == 0) {
            __threadfence();
            atomicAdd(&g_bar, 1);
            int target = NCTA_CHAIN * (j + 1);
            while (atomicAdd(&g_bar, 0) < target) __nanosleep(64);
        }
        __syncthreads();
    }
    // finalize L (final matrix in buffer 0 since PWRK even)
    if (cta0) {
        float ts = 0.f;
#pragma unroll
        for (int i = 0; i < 2; ++i) {
            int d = tid * 2 + i;
            ts += __bfloat162float(g_sAh[0][(size_t)d * (N_DIM + 1)]) +
                  __bfloat162float(g_sAl[0][(size_t)d * (N_DIM + 1)]);
        }
        red[tid] = ts;
        __syncthreads();
        for (int s = 128; s > 0; s >>= 1) { if (tid < s) red[tid] += red[tid + s]; __syncthreads(); }
        if (tid == 0) {
            float lnL = lnacc + logf(red[0]) * PINV;
            float L = expf(lnL);
            g_scal[3] = 1.f / L;
            g_scal[4] = 0.001f / L;
        }
    }
}

// ---------------- prep: transpose-split W -> Wt(hi/lo); split x ----------------
__global__ __launch_bounds__(256) void k_prepWt(const float* __restrict__ W) {
    __shared__ float t[32][33];
    int tx = threadIdx.x & 31, ty = threadIdx.x >> 5;    // 32 x 8
    int h0 = blockIdx.x * 32, n0 = blockIdx.y * 32;
#pragma unroll
    for (int i = 0; i < 4; ++i)
        t[ty + i * 8][tx] = W[(size_t)(n0 + ty + i * 8) * H_DIM + h0 + tx];
    __syncthreads();
#pragma unroll
    for (int i = 0; i < 4; ++i) {
        float vt = t[tx][ty + i * 8];                    // W[n0+tx][h0+ty+i8]
        size_t ot = (size_t)(h0 + ty + i * 8) * N_DIM + n0 + tx;
        __nv_bfloat16 ht = __float2bfloat16(vt);
        g_Wthi[ot] = ht;
        g_Wtlo[ot] = __float2bfloat16(vt - __bfloat162float(ht));
    }
}
__global__ void k_splitX(const float* __restrict__ x) {
    size_t i = ((size_t)blockIdx.x * 256 + threadIdx.x) * 4;
    float4 v = *(const float4*)&x[i];
    float vv[4] = {v.x, v.y, v.z, v.w};
#pragma unroll
    for (int j = 0; j < 4; ++j) {
        __nv_bfloat16 h = __float2bfloat16(vv[j]);
        g_xh[i + j] = h;
        g_xl[i + j] = __float2bfloat16(vv[j] - __bfloat162float(h));
    }
}

// ---------------- C = Wt Wt^T via split-4 mma, hi/lo epilogue (clone of k_mma_iter) ----
__global__ __launch_bounds__(256, 2) void k_C_mma() {
    extern __shared__ char dsm[];
    int tid = threadIdx.x, wid = tid >> 5, lane = tid & 31;
    int m0 = blockIdx.y * 128, n0 = blockIdx.x * 128;
    int wm = (wid >> 2) * 64, wn = (wid & 3) * 32;
    char* tp = (char*)(((uintptr_t)dsm + 1023) & ~(uintptr_t)1023);
    uint32_t base = smem_u32(tp);
    const uint4* pAH = (const uint4*)g_Wthi;
    const uint4* pAL = (const uint4*)g_Wtlo;

    float acc[4][4][4];
#pragma unroll
    for (int a = 0; a < 4; ++a)
#pragma unroll
        for (int b = 0; b < 4; ++b)
#pragma unroll
            for (int e = 0; e < 4; ++e) acc[a][b][e] = 0.f;

    int lrow[2], lg[2];
    uint32_t lsw[2];
#pragma unroll
    for (int j = 0; j < 2; ++j) {
        int s = tid + j * 256;
        lrow[j] = s >> 2; lg[j] = s & 3;
        lsw[j] = SW64((uint32_t)(lrow[j] * 64 + lg[j] * 16));
    }
    int lr = lane & 15, lk = (lane >> 4) * 16;

#pragma unroll
    for (int j = 0; j < 2; ++j) {
        size_t gA = (size_t)(m0 + lrow[j]) * (N_DIM / 8) + lg[j];
        size_t gB = (size_t)(n0 + lrow[j]) * (N_DIM / 8) + lg[j];
        CP_A16(base + lsw[j],          (const void*)(pAH + gA));
        CP_A16(base + 8192  + lsw[j],  (const void*)(pAL + gA));
        CP_A16(base + 16384 + lsw[j],  (const void*)(pAH + gB));
        CP_A16(base + 24576 + lsw[j],  (const void*)(pAL + gB));
    }
    CP_COMMIT();

    for (int c = 0; c < NCHU; ++c) {
        uint32_t sb = base + (uint32_t)((c & 1) * 32768);
        if (c + 1 < NCHU) {
            uint32_t nb = base + (uint32_t)(((c + 1) & 1) * 32768);
            int k4 = (c + 1) * 4;
#pragma unroll
            for (int j = 0; j < 2; ++j) {
                size_t gA = (size_t)(m0 + lrow[j]) * (N_DIM / 8) + k4 + lg[j];
                size_t gB = (size_t)(n0 + lrow[j]) * (N_DIM / 8) + k4 + lg[j];
                CP_A16(nb + lsw[j],          (const void*)(pAH + gA));
                CP_A16(nb + 8192  + lsw[j],  (const void*)(pAL + gA));
                CP_A16(nb + 16384 + lsw[j],  (const void*)(pAH + gB));
                CP_A16(nb + 24576 + lsw[j],  (const void*)(pAL + gB));
            }
            CP_COMMIT();
            CP_WAIT(1);
        } else {
            CP_WAIT(0);
        }
        __syncthreads();
#pragma unroll
        for (int ks = 0; ks < 2; ++ks) {
            uint32_t bh0[4], bh1[4], bl0[4], bl1[4];
#pragma unroll
            for (int np = 0; np < 2; ++np) {
                uint32_t sw = SW64((uint32_t)((wn + np * 16 + lr) * 64 + ks * 32 + lk));
                uint32_t r0, r1, r2, r3;
                ldsm4(r0, r1, r2, r3, sb + 16384 + sw);
                bh0[np * 2] = r0; bh0[np * 2 + 1] = r1; bh1[np * 2] = r2; bh1[np * 2 + 1] = r3;
                ldsm4(r0, r1, r2, r3, sb + 24576 + sw);
                bl0[np * 2] = r0; bl0[np * 2 + 1] = r1; bl1[np * 2] = r2; bl1[np * 2 + 1] = r3;
            }
#pragma unroll
            for (int mt = 0; mt < 4; ++mt) {
                uint32_t sw = SW64((uint32_t)((wm + mt * 16 + lr) * 64 + ks * 32 + lk));
                uint32_t a_h[4], a_l[4];
                ldsm4(a_h[0], a_h[1], a_h[2], a_h[3], sb + sw);
                ldsm4(a_l[0], a_l[1], a_l[2], a_l[3], sb + 8192 + sw);
#pragma unroll
                for (int nt = 0; nt < 4; ++nt) {
                    mma16816(acc[mt][nt], a_h, bh0[nt], bh1[nt]);
                    mma16816(acc[mt][nt], a_h, bl0[nt], bl1[nt]);
                    mma16816(acc[mt][nt], a_l, bh0[nt], bh1[nt]);
                    mma16816(acc[mt][nt], a_l, bl0[nt], bl1[nt]);   // split-4 for C
                }
            }
        }
        __syncthreads();
    }

    int rbase = lane >> 2, cpair = (lane & 3) * 2;
#pragma unroll
    for (int mt = 0; mt < 4; ++mt)
#pragma unroll
        for (int e2 = 0; e2 < 2; ++e2) {
            int m = m0 + wm + mt * 16 + rbase + e2 * 8;
#pragma unroll
            for (int nt = 0; nt < 4; ++nt) {
                size_t idx = (size_t)m * H_DIM + n0 + wn + nt * 8 + cpair;
                float v0 = acc[mt][nt][e2 * 2 + 0];
                float v1 = acc[mt][nt][e2 * 2 + 1];
                __nv_bfloat162 h2, l2;
                h2.x = __float2bfloat16(v0); h2.y = __float2bfloat16(v1);
                l2.x = __float2bfloat16(v0 - __bfloat162float(h2.x));
                l2.y = __float2bfloat16(v1 - __bfloat162float(h2.y));
                *(__nv_bfloat162*)&g_Chi[idx] = h2;
                *(__nv_bfloat162*)&g_Clo[idx] = l2;
            }
        }
}

// ---------------- u = x W via split-3 mma, fp32 epilogue (clone of k_mma_iter) ---------
__global__ __launch_bounds__(256, 2) void k_u_mma() {
    extern __shared__ char dsm[];
    int tid = threadIdx.x, wid = tid >> 5, lane = tid & 31;
    int m0 = blockIdx.y * 128, n0 = blockIdx.x * 128;
    int wm = (wid >> 2) * 64, wn = (wid & 3) * 32;
    char* tp = (char*)(((uintptr_t)dsm + 1023) & ~(uintptr_t)1023);
    uint32_t base = smem_u32(tp);
    const uint4* pAH = (const uint4*)g_xh;
    const uint4* pAL = (const uint4*)g_xl;
    const uint4* pBH = (const uint4*)g_Wthi;
    const uint4* pBL = (const uint4*)g_Wtlo;

    float acc[4][4][4];
#pragma unroll
    for (int a = 0; a < 4; ++a)
#pragma unroll
        for (int b = 0; b < 4; ++b)
#pragma unroll
            for (int e = 0; e < 4; ++e) acc[a][b][e] = 0.f;

    int lrow[2], lg[2];
    uint32_t lsw[2];
#pragma unroll
    for (int j = 0; j < 2; ++j) {
        int s = tid + j * 256;
        lrow[j] = s >> 2; lg[j] = s & 3;
        lsw[j] = SW64((uint32_t)(lrow[j] * 64 + lg[j] * 16));
    }
    int lr = lane & 15, lk = (lane >> 4) * 16;

#pragma unroll
    for (int j = 0; j < 2; ++j) {
        size_t gA = (size_t)(m0 + lrow[j]) * (N_DIM / 8) + lg[j];
        size_t gB = (size_t)(n0 + lrow[j]) * (N_DIM / 8) + lg[j];
        CP_A16(base + lsw[j],          (const void*)(pAH + gA));
        CP_A16(base + 8192  + lsw[j],  (const void*)(pAL + gA));
        CP_A16(base + 16384 + lsw[j],  (const void*)(pBH + gB));
        CP_A16(base + 24576 + lsw[j],  (const void*)(pBL + gB));
    }
    CP_COMMIT();

    for (int c = 0; c < NCHU; ++c) {
        uint32_t sb = base + (uint32_t)((c & 1) * 32768);
        if (c + 1 < NCHU) {
            uint32_t nb = base + (uint32_t)(((c + 1) & 1) * 32768);
            int k4 = (c + 1) * 4;
#pragma unroll
            for (int j = 0; j < 2; ++j) {
                size_t gA = (size_t)(m0 + lrow[j]) * (N_DIM / 8) + k4 + lg[j];
                size_t gB = (size_t)(n0 + lrow[j]) * (N_DIM / 8) + k4 + lg[j];
                CP_A16(nb + lsw[j],          (const void*)(pAH + gA));
                CP_A16(nb + 8192  + lsw[j],  (const void*)(pAL + gA));
                CP_A16(nb + 16384 + lsw[j],  (const void*)(pBH + gB));
                CP_A16(nb + 24576 + lsw[j],  (const void*)(pBL + gB));
            }
            CP_COMMIT();
            CP_WAIT(1);
        } else {
            CP_WAIT(0);
        }
        __syncthreads();
#pragma unroll
        for (int ks = 0; ks < 2; ++ks) {
            uint32_t bh0[4], bh1[4], bl0[4], bl1[4];
#pragma unroll
            for (int np = 0; np < 2; ++np) {
                uint32_t sw = SW64((uint32_t)((wn + np * 16 + lr) * 64 + ks * 32 + lk));
                uint32_t r0, r1, r2, r3;
                ldsm4(r0, r1, r2, r3, sb + 16384 + sw);
                bh0[np * 2] = r0; bh0[np * 2 + 1] = r1; bh1[np * 2] = r2; bh1[np * 2 + 1] = r3;
                ldsm4(r0, r1, r2, r3, sb + 24576 + sw);
                bl0[np * 2] = r0; bl0[np * 2 + 1] = r1; bl1[np * 2] = r2; bl1[np * 2 + 1] = r3;
            }
#pragma unroll
            for (int mt = 0; mt < 4; ++mt) {
                uint32_t sw = SW64((uint32_t)((wm + mt * 16 + lr) * 64 + ks * 32 + lk));
                uint32_t a_h[4], a_l[4];
                ldsm4(a_h[0], a_h[1], a_h[2], a_h[3], sb + sw);
                ldsm4(a_l[0], a_l[1], a_l[2], a_l[3], sb + 8192 + sw);
#pragma unroll
                for (int nt = 0; nt < 4; ++nt) {
                    mma16816(acc[mt][nt], a_h, bh0[nt], bh1[nt]);
                    mma16816(acc[mt][nt], a_h, bl0[nt], bl1[nt]);
                    mma16816(acc[mt][nt], a_l, bh0[nt], bh1[nt]);
                }
            }
        }
        __syncthreads();
    }

    int rbase = lane >> 2, cpair = (lane & 3) * 2;
#pragma unroll
    for (int mt = 0; mt < 4; ++mt)
#pragma unroll
        for (int e2 = 0; e2 < 2; ++e2) {
            int m = m0 + wm + mt * 16 + rbase + e2 * 8;
#pragma unroll
            for (int nt = 0; nt < 4; ++nt) {
                size_t idx = (size_t)m * H_DIM + n0 + wn + nt * 8 + cpair;
                *(float2*)&g_u[idx] = make_float2(acc[mt][nt][e2 * 2 + 0],
                                                  acc[mt][nt][e2 * 2 + 1]);
            }
        }
}

// ---------------- weights + iteration 0 ----------------
__global__ void k_weights(const float* __restrict__ alpha, const float* __restrict__ beta, int T) {
    int i = threadIdx.x;
    if (i >= T) return;
    float m = -1e30f;
    for (int k = 0; k < NOPS; ++k) m = fmaxf(m, alpha[i * NOPS + k]);
    float e[NOPS], s = 0.f;
    for (int k = 0; k < NOPS; ++k) { e[k] = expf(alpha[i * NOPS + k] - m); s += e[k]; }
    float invs = 1.f / s;
    for (int k = 0; k < NOPS; ++k) g_w[i * 24 + k] = e[k] * invs;
    float b0 = beta[i * 2], b1 = beta[i * 2 + 1];
    float mb = fmaxf(b0, b1);
    float e0 = expf(b0 - mb), e1 = expf(b1 - mb);
    float ib = 1.f / (e0 + e1);
    g_w[i * 24 + 20] = e0 * ib;
    g_w[i * 24 + 21] = e1 * ib;
}
__global__ void k_iter0(float* outF) {
    __shared__ float smw[24];
    int t = threadIdx.x;
    if (t < 22) smw[t] = g_w[t];
    __syncthreads();
    float invL = g_scal[3], lam = g_scal[4];
    float bw1 = smw[21];
    float mom1 = 0.25f;
    float ca = 1.f + mom1 * (1.f - bw1);
    size_t idx = ((size_t)blockIdx.x * 256 + t) * 4;
    float4 uu = *(const float4*)&g_u[idx];
    float zo[4];
    zo[0] = act_mix(uu.x * invL, smw, lam);
    zo[1] = act_mix(uu.y * invL, smw, lam);
    zo[2] = act_mix(uu.z * invL, smw, lam);
    zo[3] = act_mix(uu.w * invL, smw, lam);
    if (outF) {
        *(float4*)&outF[idx] = make_float4(zo[0], zo[1], zo[2], zo[3]);
    } else {
        *(float4*)&g_z[idx] = make_float4(zo[0], zo[1], zo[2], zo[3]);
#pragma unroll
        for (int j = 0; j < 4; ++j) {
            float za = ca * zo[j];
            __nv_bfloat16 h = __float2bfloat16(za);
            g_ah[0][idx + j] = h;
            g_al[0][idx + j] = __float2bfloat16(za - __bfloat162float(h));
        }
    }
}

// ---------------- iteration: split-3 mma + fused epilogue, 2-stage cp.async (proven) ---
__global__ __launch_bounds__(256, 2) void k_mma_iter(int inSel, int outSel, float* outF,
                                                     int iter, float mom_next, int is_last) {
    extern __shared__ char dsm[];
    __shared__ float smw[24];

    const __nv_bfloat16* __restrict__ ah = g_ah[inSel];
    const __nv_bfloat16* __restrict__ al = g_al[inSel];
    __nv_bfloat16* __restrict__ aho = g_ah[outSel];
    __nv_bfloat16* __restrict__ alo = g_al[outSel];

    int tid = threadIdx.x, wid = tid >> 5, lane = tid & 31;
    int m0 = blockIdx.y * 128, n0 = blockIdx.x * 128;
    int wm = (wid >> 2) * 64, wn = (wid & 3) * 32;

    char* tp = (char*)(((uintptr_t)dsm + 1023) & ~(uintptr_t)1023);
    uint32_t base = smem_u32(tp);
    if (tid < 22) smw[tid] = g_w[iter * 24 + tid];

    const uint4* pAH = (const uint4*)ah;
    const uint4* pAL = (const uint4*)al;
    const uint4* pBH = (const uint4*)g_Chi;
    const uint4* pBL = (const uint4*)g_Clo;

    float acc[4][4][4];
#pragma unroll
    for (int a = 0; a < 4; ++a)
#pragma unroll
        for (int b = 0; b < 4; ++b)
#pragma unroll
            for (int e = 0; e < 4; ++e) acc[a][b][e] = 0.f;

    int lrow[2], lg[2];
    uint32_t lsw[2];
#pragma unroll
    for (int j = 0; j < 2; ++j) {
        int s = tid + j * 256;
        lrow[j] = s >> 2; lg[j] = s & 3;
        lsw[j] = SW64((uint32_t)(lrow[j] * 64 + lg[j] * 16));
    }
    int lr = lane & 15, lk = (lane >> 4) * 16;

#pragma unroll
    for (int j = 0; j < 2; ++j) {
        size_t gA = (size_t)(m0 + lrow[j]) * (H_DIM / 8) + lg[j];
        size_t gB = (size_t)(n0 + lrow[j]) * (H_DIM / 8) + lg[j];
        CP_A16(base + lsw[j],          (const void*)(pAH + gA));
        CP_A16(base + 8192  + lsw[j],  (const void*)(pAL + gA));
        CP_A16(base + 16384 + lsw[j],  (const void*)(pBH + gB));
        CP_A16(base + 24576 + lsw[j],  (const void*)(pBL + gB));
    }
    CP_COMMIT();

    for (int c = 0; c < NCH2; ++c) {
        uint32_t sb = base + (uint32_t)((c & 1) * 32768);
        if (c + 1 < NCH2) {
            uint32_t nb = base + (uint32_t)(((c + 1) & 1) * 32768);
            int k4 = (c + 1) * 4;
#pragma unroll
            for (int j = 0; j < 2; ++j) {
                size_t gA = (size_t)(m0 + lrow[j]) * (H_DIM / 8) + k4 + lg[j];
                size_t gB = (size_t)(n0 + lrow[j]) * (H_DIM / 8) + k4 + lg[j];
                CP_A16(nb + lsw[j],          (const void*)(pAH + gA));
                CP_A16(nb + 8192  + lsw[j],  (const void*)(pAL + gA));
                CP_A16(nb + 16384 + lsw[j],  (const void*)(pBH + gB));
                CP_A16(nb + 24576 + lsw[j],  (const void*)(pBL + gB));
            }
            CP_COMMIT();
            CP_WAIT(1);
        } else {
            CP_WAIT(0);
        }
        __syncthreads();
#pragma unroll
        for (int ks = 0; ks < 2; ++ks) {
            uint32_t bh0[4], bh1[4], bl0[4], bl1[4];
#pragma unroll
            for (int np = 0; np < 2; ++np) {
                uint32_t sw = SW64((uint32_t)((wn + np * 16 + lr) * 64 + ks * 32 + lk));
                uint32_t r0, r1, r2, r3;
                ldsm4(r0, r1, r2, r3, sb + 16384 + sw);
                bh0[np * 2] = r0; bh0[np * 2 + 1] = r1; bh1[np * 2] = r2; bh1[np * 2 + 1] = r3;
                ldsm4(r0, r1, r2, r3, sb + 24576 + sw);
                bl0[np * 2] = r0; bl0[np * 2 + 1] = r1; bl1[np * 2] = r2; bl1[np * 2 + 1] = r3;
            }
#pragma unroll
            for (int mt = 0; mt < 4; ++mt) {
                uint32_t sw = SW64((uint32_t)((wm + mt * 16 + lr) * 64 + ks * 32 + lk));
                uint32_t a_h[4], a_l[4];
                ldsm4(a_h[0], a_h[1], a_h[2], a_h[3], sb + sw);
                ldsm4(a_l[0], a_l[1], a_l[2], a_l[3], sb + 8192 + sw);
#pragma unroll
                for (int nt = 0; nt < 4; ++nt) {
                    mma16816(acc[mt][nt], a_h, bh0[nt], bh1[nt]);
                    mma16816(acc[mt][nt], a_h, bl0[nt], bl1[nt]);
                    mma16816(acc[mt][nt], a_l, bh0[nt], bh1[nt]);
                }
            }
        }
        __syncthreads();
    }

    // ---- fused epilogue straight from register accumulators ----
    float invL = g_scal[3], lam = g_scal[4];
    float bw0 = smw[20], bw1 = smw[21];
    float ca = 1.f + mom_next * (1.f - bw1);
    float cb = mom_next * bw0;
    int rbase = lane >> 2, cpair = (lane & 3) * 2;
#pragma unroll
    for (int mt = 0; mt < 4; ++mt) {
#pragma unroll
        for (int e2 = 0; e2 < 2; ++e2) {
            int m = m0 + wm + mt * 16 + rbase + e2 * 8;
            size_t rowoff = (size_t)m * H_DIM;
#pragma unroll
            for (int nt = 0; nt < 4; ++nt) {
                size_t idx = rowoff + n0 + wn + nt * 8 + cpair;
                float d0 = acc[mt][nt][e2 * 2 + 0];
                float d1 = acc[mt][nt][e2 * 2 + 1];
                __nv_bfloat162 h2 = *(const __nv_bfloat162*)&ah[idx];
                __nv_bfloat162 l2 = *(const __nv_bfloat162*)&al[idx];
                float2 u2 = *(const float2*)&g_u[idx];
                float za0 = __bfloat162float(h2.x) + __bfloat162float(l2.x);
                float za1 = __bfloat162float(h2.y) + __bfloat162float(l2.y);
                float zg0 = za0 - (d0 - u2.x) * invL;
                float zg1 = za1 - (d1 - u2.y) * invL;
                float zop0 = act_mix(zg0, smw, lam);
                float zop1 = act_mix(zg1, smw, lam);
                if (is_last) {
                    *(float2*)&outF[idx] = make_float2(zop0, zop1);
                } else {
                    float2 z2 = *(const float2*)&g_z[idx];
                    *(float2*)&g_z[idx] = make_float2(zop0, zop1);
                    float zan0 = ca * zop0 - cb * z2.x;
                    float zan1 = ca * zop1 - cb * z2.y;
                    __nv_bfloat162 ho, lo2;
                    ho.x = __float2bfloat16(zan0);
                    ho.y = __float2bfloat16(zan1);
                    lo2.x = __float2bfloat16(zan0 - __bfloat162float(ho.x));
                    lo2.y = __float2bfloat16(zan1 - __bfloat162float(ho.y));
                    *(__nv_bfloat162*)&aho[idx] = ho;
                    *(__nv_bfloat162*)&alo[idx] = lo2;
                }
            }
        }
    }
}

// ---------------- host orchestration (graph-capturable: kernel launches only) ----------------
extern "C" void kernel_launch(void* const* d_in, const int* in_sizes, int n_in,
                              void* d_out, int out_size) {
    const float* x     = (const float*)d_in[0];
    const float* W     = (const float*)d_in[1];
    const float* alpha = (const float*)d_in[2];
    const float* lbeta = (const float*)d_in[3];
    float* out = (float*)d_out;
    int T = in_sizes[2] / NOPS;
    if (T < 1) T = 1;
    if (T > 16) T = 16;

    const int DSM = 2 * 32768 + 1024;   // double-buffered stages + align slack
    cudaFuncSetAttribute(k_mma_iter, cudaFuncAttributeMaxDynamicSharedMemorySize, DSM);
    cudaFuncSetAttribute(k_C_mma,   cudaFuncAttributeMaxDynamicSharedMemorySize, DSM);
    cudaFuncSetAttribute(k_u_mma,   cudaFuncAttributeMaxDynamicSharedMemorySize, DSM);

    dim3 thr(256);

    // Spectral norm: A0 = WW^T (fp32 SIMT, split epilogue + barrier reset),
    // then ONE persistent kernel for 10 squarings + L finalize.
    k_wwT64<<<dim3(8, 8), thr>>>(W);
    k_chain<<<dim3(8, 8), thr>>>();

    // Splits, then C and u on tensor cores
    k_prepWt<<<dim3(H_DIM / 32, N_DIM / 32), thr>>>(W);
    k_splitX<<<(B_DIM * N_DIM) / (256 * 4), thr>>>(x);
    k_C_mma<<<dim3(8, 8), thr, DSM>>>();
    k_u_mma<<<dim3(8, 32), thr, DSM>>>();
    k_weights<<<1, 32>>>(alpha, lbeta, T);

    // Iteration 0 (z = zprev = 0): elementwise
    k_iter0<<<(B_DIM * H_DIM) / (256 * 4), thr>>>((T == 1) ? out : nullptr);

    // Iterations 1..T-1: mma.sync fused GEMM + epilogue
    for (int i = 1; i < T; ++i) {
        float mom_next = (float)((double)(i + 1) / (double)(i + 4));
        int inSel  = (i + 1) & 1;
        int outSel = i & 1;
        int last = (i == T - 1);
        k_mma_iter<<<dim3(8, 32), thr, DSM>>>(inSel, outSel, last ? out : nullptr,
                                              i, mom_next, last);
    }
}

// round 17
// speedup vs baseline: 2.5022x; 1.1485x over previous
#include <cuda_runtime.h>
#include <cuda_bf16.h>
#include <math.h>
#include <stdint.h>

#define B_DIM 4096
#define N_DIM 512
#define H_DIM 1024
#define NOPS  20
#define PWRK  10               // squarings -> p = 2^10 = 1024
#define PINV  (1.0f/1024.0f)
#define KC2   32               // K chunk (bf16 cols) per stage
#define NCH2  (H_DIM / KC2)    // 32 chunks (iteration GEMM)
#define NCHU  (N_DIM / KC2)    // 16 chunks (u / C GEMMs)
#define NCTA_CHAIN 64

#define SW128(o) ((o) ^ (((o) >> 3) & 0x70))
#define SW64(o)  ((o) ^ (((o) >> 3) & 0x30))

// ---------------- static device scratch (no allocations allowed) ----------------
static __device__ __align__(16) __nv_bfloat16 g_Wthi[H_DIM * N_DIM];          // W^T hi
static __device__ __align__(16) __nv_bfloat16 g_Wtlo[H_DIM * N_DIM];          // W^T lo
static __device__ __align__(16) __nv_bfloat16 g_xh[(size_t)B_DIM * N_DIM];    // x hi
static __device__ __align__(16) __nv_bfloat16 g_xl[(size_t)B_DIM * N_DIM];    // x lo
static __device__ __align__(16) __nv_bfloat16 g_Chi[H_DIM * H_DIM];           // C hi
static __device__ __align__(16) __nv_bfloat16 g_Clo[H_DIM * H_DIM];           // C lo
static __device__ __align__(16) __nv_bfloat16 g_sAh[2][N_DIM * N_DIM];        // chain ping-pong hi
static __device__ __align__(16) __nv_bfloat16 g_sAl[2][N_DIM * N_DIM];        // chain ping-pong lo
static __device__ float g_u[(size_t)B_DIM * H_DIM];                           // W^T x
static __device__ float g_z[(size_t)B_DIM * H_DIM];                           // current z (fp32)
static __device__ __align__(16) __nv_bfloat16 g_ah[2][(size_t)B_DIM * H_DIM]; // z_aux hi ping-pong
static __device__ __align__(16) __nv_bfloat16 g_al[2][(size_t)B_DIM * H_DIM]; // z_aux lo ping-pong
static __device__ float g_scal[8];   // [3]=1/L, [4]=lam
static __device__ float g_w[16 * 24];
static __device__ int   g_bar;       // chain barrier counter (zeroed by k_wwT64 each replay)

// ---------------- PTX helpers (sm_80+ baseline: ldmatrix / mma.sync / cp.async) --------
__device__ __forceinline__ uint32_t smem_u32(const void* p) {
    uint32_t a;
    asm("{ .reg .u64 t; cvta.to.shared.u64 t, %1; cvt.u32.u64 %0, t; }" : "=r"(a) : "l"(p));
    return a;
}
__device__ __forceinline__ void ldsm4(uint32_t& r0, uint32_t& r1, uint32_t& r2, uint32_t& r3,
                                      uint32_t addr) {
    asm volatile("ldmatrix.sync.aligned.m8n8.x4.shared.b16 {%0,%1,%2,%3}, [%4];"
                 : "=r"(r0), "=r"(r1), "=r"(r2), "=r"(r3) : "r"(addr));
}
__device__ __forceinline__ void mma16816(float* d, const uint32_t* a, uint32_t b0, uint32_t b1) {
    asm volatile(
        "mma.sync.aligned.m16n8k16.row.col.f32.bf16.bf16.f32 "
        "{%0,%1,%2,%3}, {%4,%5,%6,%7}, {%8,%9}, {%0,%1,%2,%3};"
        : "+f"(d[0]), "+f"(d[1]), "+f"(d[2]), "+f"(d[3])
        : "r"(a[0]), "r"(a[1]), "r"(a[2]), "r"(a[3]), "r"(b0), "r"(b1));
}
__device__ __forceinline__ float rcpf(float x) {
    float r; asm("rcp.approx.ftz.f32 %0, %1;" : "=f"(r) : "f"(x)); return r;
}
#define CP_A16(dst, src) asm volatile("cp.async.cg.shared.global [%0], [%1], 16;" :: "r"(dst), "l"(src))
#define CP_COMMIT()      asm volatile("cp.async.commit_group;" ::: "memory")
#define CP_WAIT(n)       asm volatile("cp.async.wait_group %0;" :: "n"(n) : "memory")

// ---------------- 20-op activation mixture (MUFU-minimized: 1 rcp for 4 denominators) --
__device__ __forceinline__ float act_mix(float v, const float* aw, float lam) {
    float av  = fabsf(v);
    float e   = __expf(-av);
    float e2  = e * e;
    bool pos  = (v >= 0.f);
    float a1 = 1.f + e;
    float a2 = 1.f + e2;
    // mish denominator/numerator in e (algebraic, no sig dependency):
    //   v>=0: tanh(sp) = (1+2e)/(1+2e+2e^2);  v<0: (2e+e^2)/(2+2e+e^2)
    float num3 = pos ? fmaf(2.f, e, 1.f) : fmaf(e, e, e + e);
    float a3   = pos ? fmaf(2.f, e2, fmaf(2.f, e, 1.f)) : fmaf(e, e, fmaf(2.f, e, 2.f));
    float a4 = 1.f + av;
    float p12 = a1 * a2, p34 = a3 * a4;
    float rD = rcpf(p12 * p34);
    float i1e = rD * a2 * p34;     // 1/(1+e)
    float r2  = rD * a1 * p34;     // 1/(1+e2)
    float r3  = rD * p12 * a4;     // 1/a3
    float r4  = rD * p12 * a3;     // 1/(1+av)

    float sig = pos ? i1e : e * i1e;
    float sp  = fmaxf(v, 0.f) + __logf(a1);
    float th  = (1.f - e2) * r2;   th = pos ? th : -th;
    float msh = num3 * r3;
    float erv = erff(v * 0.70710678118654752f);
    float em1 = e - 1.f;                       // expm1(v) for v<0
    float elu = (v > 0.f) ? v : em1;
    float r6  = fminf(fmaxf(v + 3.f, 0.f), 6.f) * (1.f / 6.f);

    float r;
    r  = aw[0]  * ((v > lam) ? (v - lam) : ((v < -lam) ? (v + lam) : 0.f));
    r += aw[1]  * fmaxf(v, 0.f);
    r += aw[2]  * v;
    r += aw[3]  * (0.5f * v * (1.f + erv));
    r += aw[4]  * elu;
    r += aw[5]  * ((av > lam) ? v : 0.f);
    r += aw[6]  * fminf(fmaxf(v, -1.f), 1.f);
    r += aw[7]  * (v * r6);
    r += aw[8]  * (1.0507009873554805f * ((v > 0.f) ? v : 1.6732632423543772f * em1));
    r += aw[9]  * elu;
    r += aw[10] * ((v >= 0.f) ? v : 0.01f * v);
    r += aw[11] * (v - sp);
    r += aw[12] * (v - th);
    r += aw[13] * (v * r4);
    r += aw[14] * sp;
    r += aw[15] * th;
    r += aw[16] * sig;
    r += aw[17] * r6;
    r += aw[18] * (v * sig);
    r += aw[19] * (v * msh);
    return r;
}

// ---------------- A0 = W W^T [512x512], fp32 SIMT, epilogue emits bf16 hi/lo ----------------
__device__ __forceinline__ void ld64_T(float s[16][64], const float* src,
                                       int m0, int k0, int ld, int t) {
    int row = t >> 2, cv = (t & 3) * 4;
    float4 v = *(const float4*)&src[(size_t)(m0 + row) * ld + k0 + cv];
    s[cv + 0][row] = v.x; s[cv + 1][row] = v.y; s[cv + 2][row] = v.z; s[cv + 3][row] = v.w;
}
__device__ __forceinline__ void mma64(const float (*a)[64], const float (*b)[64],
                                      int tx, int ty, float acc[4][4]) {
#pragma unroll
    for (int kk = 0; kk < 16; ++kk) {
        float ar[4], br[4];
        *(float4*)ar = *(const float4*)&a[kk][ty * 4];
        *(float4*)br = *(const float4*)&b[kk][tx * 4];
#pragma unroll
        for (int i = 0; i < 4; ++i)
#pragma unroll
            for (int j = 0; j < 4; ++j)
                acc[i][j] = fmaf(ar[i], br[j], acc[i][j]);
    }
}
__global__ __launch_bounds__(256) void k_wwT64(const float* __restrict__ W) {
    __shared__ float a[16][64], b[16][64];
    int t = threadIdx.x, tx = t & 15, ty = t >> 4;
    int n0 = blockIdx.x * 64, m0 = blockIdx.y * 64;
    if (blockIdx.x == 0 && blockIdx.y == 0 && t == 0) g_bar = 0;   // reset chain barrier
    float acc[4][4] = {};
    for (int k0 = 0; k0 < H_DIM; k0 += 16) {
        ld64_T(a, W, m0, k0, H_DIM, t);
        ld64_T(b, W, n0, k0, H_DIM, t);
        __syncthreads();
        mma64(a, b, tx, ty, acc);
        __syncthreads();
    }
#pragma unroll
    for (int i = 0; i < 4; ++i)
#pragma unroll
        for (int j = 0; j < 4; ++j) {
            float v = acc[i][j];
            size_t o = (size_t)(m0 + ty * 4 + i) * N_DIM + n0 + tx * 4 + j;
            __nv_bfloat16 h = __float2bfloat16(v);
            g_sAh[0][o] = h;
            g_sAl[0][o] = __float2bfloat16(v - __bfloat162float(h));
        }
}

// ---------------- persistent spectral chain: 10 squarings + L, one kernel ----------------
// grid (8,8)=64 CTAs (co-resident), 256 threads (8 warps, warp tile 16x32).
__global__ __launch_bounds__(256) void k_chain() {
    __shared__ __align__(16) char sm[32768];    // Ah 8K | Al 8K | Bh 8K | Bl 8K
    __shared__ float red[256];
    __shared__ float s_tr;
    int tid = threadIdx.x, wid = tid >> 5, lane = tid & 31;
    int m0 = blockIdx.y * 64, n0 = blockIdx.x * 64;
    int wm = (wid & 3) * 16, wn = (wid >> 2) * 32;   // 4x2 warp grid, tile 16x32
    int cta0 = (blockIdx.x == 0 && blockIdx.y == 0);
    uint32_t bAh = smem_u32(sm);
    int lr = lane & 15, lk = (lane >> 4) * 16;
    int rbase = lane >> 2, cpair = (lane & 3) * 2;
    float lnacc = 0.f;

    for (int j = 0; j < PWRK; ++j) {
        int src = j & 1;
        const __nv_bfloat16* Ah = g_sAh[src];
        const __nv_bfloat16* Al = g_sAl[src];
        __nv_bfloat16* Oh = g_sAh[src ^ 1];
        __nv_bfloat16* Ol = g_sAl[src ^ 1];
        float ts = 0.f;
#pragma unroll
        for (int i = 0; i < 2; ++i) {
            int d = tid * 2 + i;
            ts += __bfloat162float(Ah[(size_t)d * (N_DIM + 1)]) +
                  __bfloat162float(Al[(size_t)d * (N_DIM + 1)]);
        }
        red[tid] = ts;
        __syncthreads();
        for (int s = 128; s > 0; s >>= 1) { if (tid < s) red[tid] += red[tid + s]; __syncthreads(); }
        if (tid == 0) s_tr = red[0];
        __syncthreads();
        float tr = s_tr;
        if (cta0 && tid == 0) lnacc += logf(tr) * ldexpf(1.f, -j);

        const uint4* pAh = (const uint4*)Ah;
        const uint4* pAl = (const uint4*)Al;
        float acc[4][4];
#pragma unroll
        for (int b = 0; b < 4; ++b)
#pragma unroll
            for (int e = 0; e < 4; ++e) acc[b][e] = 0.f;

        for (int c = 0; c < 8; ++c) {               // K=512 in chunks of 64
            __syncthreads();
#pragma unroll
            for (int jj = 0; jj < 2; ++jj) {
                int s = tid + jj * 256;
                int row = s >> 3, g = s & 7;
                uint32_t sw = SW128((uint32_t)(row * 128 + g * 16));
                size_t gi = (size_t)(m0 + row) * 64 + c * 8 + g;
                size_t gj = (size_t)(n0 + row) * 64 + c * 8 + g;
                *(uint4*)(sm + sw)         = pAh[gi];
                *(uint4*)(sm + 8192 + sw)  = pAl[gi];
                *(uint4*)(sm + 16384 + sw) = pAh[gj];
                *(uint4*)(sm + 24576 + sw) = pAl[gj];
            }
            __syncthreads();
#pragma unroll
            for (int ks = 0; ks < 4; ++ks) {
                uint32_t bh0[4], bh1[4], bl0[4], bl1[4];
#pragma unroll
                for (int np = 0; np < 2; ++np) {
                    uint32_t sw = SW128((uint32_t)((wn + np * 16 + lr) * 128 + ks * 32 + lk));
                    uint32_t r0, r1, r2, r3;
                    ldsm4(r0, r1, r2, r3, bAh + 16384 + sw);
                    bh0[np * 2] = r0; bh0[np * 2 + 1] = r1; bh1[np * 2] = r2; bh1[np * 2 + 1] = r3;
                    ldsm4(r0, r1, r2, r3, bAh + 24576 + sw);
                    bl0[np * 2] = r0; bl0[np * 2 + 1] = r1; bl1[np * 2] = r2; bl1[np * 2 + 1] = r3;
                }
                uint32_t sw = SW128((uint32_t)((wm + lr) * 128 + ks * 32 + lk));
                uint32_t a_h[4], a_l[4];
                ldsm4(a_h[0], a_h[1], a_h[2], a_h[3], bAh + sw);
                ldsm4(a_l[0], a_l[1], a_l[2], a_l[3], bAh + 8192 + sw);
#pragma unroll
                for (int nt = 0; nt < 4; ++nt) {
                    mma16816(acc[nt], a_h, bh0[nt], bh1[nt]);
                    mma16816(acc[nt], a_h, bl0[nt], bl1[nt]);
                    mma16816(acc[nt], a_l, bh0[nt], bh1[nt]);
                    mma16816(acc[nt], a_l, bl0[nt], bl1[nt]);
                }
            }
        }
        float sc = 1.f / (tr * tr);
#pragma unroll
        for (int e2 = 0; e2 < 2; ++e2) {
            int m = m0 + wm + rbase + e2 * 8;
#pragma unroll
            for (int nt = 0; nt < 4; ++nt) {
                size_t idx = (size_t)m * N_DIM + n0 + wn + nt * 8 + cpair;
                float v0 = acc[nt][e2 * 2 + 0] * sc;
                float v1 = acc[nt][e2 * 2 + 1] * sc;
                __nv_bfloat162 h2, l2;
                h2.x = __float2bfloat16(v0); h2.y = __float2bfloat16(v1);
                l2.x = __float2bfloat16(v0 - __bfloat162float(h2.x));
                l2.y = __float2bfloat16(v1 - __bfloat162float(h2.y));
                *(__nv_bfloat162*)&Oh[idx] = h2;
                *(__nv_bfloat162*)&Ol[idx] = l2;
            }
        }
        __syncthreads();
        if (tid == 0) {
            __threadfence();
            atomicAdd(&g_bar, 1);
            int target = NCTA_CHAIN * (j + 1);
            while (atomicAdd(&g_bar, 0) < target) __nanosleep(64);
        }
        __syncthreads();
    }
    if (cta0) {
        float ts = 0.f;
#pragma unroll
        for (int i = 0; i < 2; ++i) {
            int d = tid * 2 + i;
            ts += __bfloat162float(g_sAh[0][(size_t)d * (N_DIM + 1)]) +
                  __bfloat162float(g_sAl[0][(size_t)d * (N_DIM + 1)]);
        }
        red[tid] = ts;
        __syncthreads();
        for (int s = 128; s > 0; s >>= 1) { if (tid < s) red[tid] += red[tid + s]; __syncthreads(); }
        if (tid == 0) {
            float lnL = lnacc + logf(red[0]) * PINV;
            float L = expf(lnL);
            g_scal[3] = 1.f / L;
            g_scal[4] = 0.001f / L;
        }
    }
}

// ---------------- prep: transpose-split W -> Wt(hi/lo); split x ----------------
__global__ __launch_bounds__(256) void k_prepWt(const float* __restrict__ W) {
    __shared__ float t[32][33];
    int tx = threadIdx.x & 31, ty = threadIdx.x >> 5;    // 32 x 8
    int h0 = blockIdx.x * 32, n0 = blockIdx.y * 32;
#pragma unroll
    for (int i = 0; i < 4; ++i)
        t[ty + i * 8][tx] = W[(size_t)(n0 + ty + i * 8) * H_DIM + h0 + tx];
    __syncthreads();
#pragma unroll
    for (int i = 0; i < 4; ++i) {
        float vt = t[tx][ty + i * 8];
        size_t ot = (size_t)(h0 + ty + i * 8) * N_DIM + n0 + tx;
        __nv_bfloat16 ht = __float2bfloat16(vt);
        g_Wthi[ot] = ht;
        g_Wtlo[ot] = __float2bfloat16(vt - __bfloat162float(ht));
    }
}
__global__ void k_splitX(const float* __restrict__ x) {
    size_t i = ((size_t)blockIdx.x * 256 + threadIdx.x) * 4;
    float4 v = *(const float4*)&x[i];
    float vv[4] = {v.x, v.y, v.z, v.w};
#pragma unroll
    for (int j = 0; j < 4; ++j) {
        __nv_bfloat16 h = __float2bfloat16(vv[j]);
        g_xh[i + j] = h;
        g_xl[i + j] = __float2bfloat16(vv[j] - __bfloat162float(h));
    }
}

// ---------------- C = Wt Wt^T via split-4 mma, hi/lo epilogue ----------------
__global__ __launch_bounds__(256, 2) void k_C_mma() {
    extern __shared__ char dsm[];
    int tid = threadIdx.x, wid = tid >> 5, lane = tid & 31;
    int m0 = blockIdx.y * 128, n0 = blockIdx.x * 128;
    int wm = (wid >> 2) * 64, wn = (wid & 3) * 32;
    char* tp = (char*)(((uintptr_t)dsm + 1023) & ~(uintptr_t)1023);
    uint32_t base = smem_u32(tp);
    const uint4* pAH = (const uint4*)g_Wthi;
    const uint4* pAL = (const uint4*)g_Wtlo;

    float acc[4][4][4];
#pragma unroll
    for (int a = 0; a < 4; ++a)
#pragma unroll
        for (int b = 0; b < 4; ++b)
#pragma unroll
            for (int e = 0; e < 4; ++e) acc[a][b][e] = 0.f;

    int lrow[2], lg[2];
    uint32_t lsw[2];
#pragma unroll
    for (int j = 0; j < 2; ++j) {
        int s = tid + j * 256;
        lrow[j] = s >> 2; lg[j] = s & 3;
        lsw[j] = SW64((uint32_t)(lrow[j] * 64 + lg[j] * 16));
    }
    int lr = lane & 15, lk = (lane >> 4) * 16;

#pragma unroll
    for (int j = 0; j < 2; ++j) {
        size_t gA = (size_t)(m0 + lrow[j]) * (N_DIM / 8) + lg[j];
        size_t gB = (size_t)(n0 + lrow[j]) * (N_DIM / 8) + lg[j];
        CP_A16(base + lsw[j],          (const void*)(pAH + gA));
        CP_A16(base + 8192  + lsw[j],  (const void*)(pAL + gA));
        CP_A16(base + 16384 + lsw[j],  (const void*)(pAH + gB));
        CP_A16(base + 24576 + lsw[j],  (const void*)(pAL + gB));
    }
    CP_COMMIT();

    for (int c = 0; c < NCHU; ++c) {
        uint32_t sb = base + (uint32_t)((c & 1) * 32768);
        if (c + 1 < NCHU) {
            uint32_t nb = base + (uint32_t)(((c + 1) & 1) * 32768);
            int k4 = (c + 1) * 4;
#pragma unroll
            for (int j = 0; j < 2; ++j) {
                size_t gA = (size_t)(m0 + lrow[j]) * (N_DIM / 8) + k4 + lg[j];
                size_t gB = (size_t)(n0 + lrow[j]) * (N_DIM / 8) + k4 + lg[j];
                CP_A16(nb + lsw[j],          (const void*)(pAH + gA));
                CP_A16(nb + 8192  + lsw[j],  (const void*)(pAL + gA));
                CP_A16(nb + 16384 + lsw[j],  (const void*)(pAH + gB));
                CP_A16(nb + 24576 + lsw[j],  (const void*)(pAL + gB));
            }
            CP_COMMIT();
            CP_WAIT(1);
        } else {
            CP_WAIT(0);
        }
        __syncthreads();
#pragma unroll
        for (int ks = 0; ks < 2; ++ks) {
            uint32_t bh0[4], bh1[4], bl0[4], bl1[4];
#pragma unroll
            for (int np = 0; np < 2; ++np) {
                uint32_t sw = SW64((uint32_t)((wn + np * 16 + lr) * 64 + ks * 32 + lk));
                uint32_t r0, r1, r2, r3;
                ldsm4(r0, r1, r2, r3, sb + 16384 + sw);
                bh0[np * 2] = r0; bh0[np * 2 + 1] = r1; bh1[np * 2] = r2; bh1[np * 2 + 1] = r3;
                ldsm4(r0, r1, r2, r3, sb + 24576 + sw);
                bl0[np * 2] = r0; bl0[np * 2 + 1] = r1; bl1[np * 2] = r2; bl1[np * 2 + 1] = r3;
            }
#pragma unroll
            for (int mt = 0; mt < 4; ++mt) {
                uint32_t sw = SW64((uint32_t)((wm + mt * 16 + lr) * 64 + ks * 32 + lk));
                uint32_t a_h[4], a_l[4];
                ldsm4(a_h[0], a_h[1], a_h[2], a_h[3], sb + sw);
                ldsm4(a_l[0], a_l[1], a_l[2], a_l[3], sb + 8192 + sw);
#pragma unroll
                for (int nt = 0; nt < 4; ++nt) {
                    mma16816(acc[mt][nt], a_h, bh0[nt], bh1[nt]);
                    mma16816(acc[mt][nt], a_h, bl0[nt], bl1[nt]);
                    mma16816(acc[mt][nt], a_l, bh0[nt], bh1[nt]);
                    mma16816(acc[mt][nt], a_l, bl0[nt], bl1[nt]);
                }
            }
        }
        __syncthreads();
    }

    int rbase = lane >> 2, cpair = (lane & 3) * 2;
#pragma unroll
    for (int mt = 0; mt < 4; ++mt)
#pragma unroll
        for (int e2 = 0; e2 < 2; ++e2) {
            int m = m0 + wm + mt * 16 + rbase + e2 * 8;
#pragma unroll
            for (int nt = 0; nt < 4; ++nt) {
                size_t idx = (size_t)m * H_DIM + n0 + wn + nt * 8 + cpair;
                float v0 = acc[mt][nt][e2 * 2 + 0];
                float v1 = acc[mt][nt][e2 * 2 + 1];
                __nv_bfloat162 h2, l2;
                h2.x = __float2bfloat16(v0); h2.y = __float2bfloat16(v1);
                l2.x = __float2bfloat16(v0 - __bfloat162float(h2.x));
                l2.y = __float2bfloat16(v1 - __bfloat162float(h2.y));
                *(__nv_bfloat162*)&g_Chi[idx] = h2;
                *(__nv_bfloat162*)&g_Clo[idx] = l2;
            }
        }
}

// ---------------- u = x W via split-3 mma, fp32 epilogue ----------------
__global__ __launch_bounds__(256, 2) void k_u_mma() {
    extern __shared__ char dsm[];
    int tid = threadIdx.x, wid = tid >> 5, lane = tid & 31;
    int m0 = blockIdx.y * 128, n0 = blockIdx.x * 128;
    int wm = (wid >> 2) * 64, wn = (wid & 3) * 32;
    char* tp = (char*)(((uintptr_t)dsm + 1023) & ~(uintptr_t)1023);
    uint32_t base = smem_u32(tp);
    const uint4* pAH = (const uint4*)g_xh;
    const uint4* pAL = (const uint4*)g_xl;
    const uint4* pBH = (const uint4*)g_Wthi;
    const uint4* pBL = (const uint4*)g_Wtlo;

    float acc[4][4][4];
#pragma unroll
    for (int a = 0; a < 4; ++a)
#pragma unroll
        for (int b = 0; b < 4; ++b)
#pragma unroll
            for (int e = 0; e < 4; ++e) acc[a][b][e] = 0.f;

    int lrow[2], lg[2];
    uint32_t lsw[2];
#pragma unroll
    for (int j = 0; j < 2; ++j) {
        int s = tid + j * 256;
        lrow[j] = s >> 2; lg[j] = s & 3;
        lsw[j] = SW64((uint32_t)(lrow[j] * 64 + lg[j] * 16));
    }
    int lr = lane & 15, lk = (lane >> 4) * 16;

#pragma unroll
    for (int j = 0; j < 2; ++j) {
        size_t gA = (size_t)(m0 + lrow[j]) * (N_DIM / 8) + lg[j];
        size_t gB = (size_t)(n0 + lrow[j]) * (N_DIM / 8) + lg[j];
        CP_A16(base + lsw[j],          (const void*)(pAH + gA));
        CP_A16(base + 8192  + lsw[j],  (const void*)(pAL + gA));
        CP_A16(base + 16384 + lsw[j],  (const void*)(pBH + gB));
        CP_A16(base + 24576 + lsw[j],  (const void*)(pBL + gB));
    }
    CP_COMMIT();

    for (int c = 0; c < NCHU; ++c) {
        uint32_t sb = base + (uint32_t)((c & 1) * 32768);
        if (c + 1 < NCHU) {
            uint32_t nb = base + (uint32_t)(((c + 1) & 1) * 32768);
            int k4 = (c + 1) * 4;
#pragma unroll
            for (int j = 0; j < 2; ++j) {
                size_t gA = (size_t)(m0 + lrow[j]) * (N_DIM / 8) + k4 + lg[j];
                size_t gB = (size_t)(n0 + lrow[j]) * (N_DIM / 8) + k4 + lg[j];
                CP_A16(nb + lsw[j],          (const void*)(pAH + gA));
                CP_A16(nb + 8192  + lsw[j],  (const void*)(pAL + gA));
                CP_A16(nb + 16384 + lsw[j],  (const void*)(pBH + gB));
                CP_A16(nb + 24576 + lsw[j],  (const void*)(pBL + gB));
            }
            CP_COMMIT();
            CP_WAIT(1);
        } else {
            CP_WAIT(0);
        }
        __syncthreads();
#pragma unroll
        for (int ks = 0; ks < 2; ++ks) {
            uint32_t bh0[4], bh1[4], bl0[4], bl1[4];
#pragma unroll
            for (int np = 0; np < 2; ++np) {
                uint32_t sw = SW64((uint32_t)((wn + np * 16 + lr) * 64 + ks * 32 + lk));
                uint32_t r0, r1, r2, r3;
                ldsm4(r0, r1, r2, r3, sb + 16384 + sw);
                bh0[np * 2] = r0; bh0[np * 2 + 1] = r1; bh1[np * 2] = r2; bh1[np * 2 + 1] = r3;
                ldsm4(r0, r1, r2, r3, sb + 24576 + sw);
                bl0[np * 2] = r0; bl0[np * 2 + 1] = r1; bl1[np * 2] = r2; bl1[np * 2 + 1] = r3;
            }
#pragma unroll
            for (int mt = 0; mt < 4; ++mt) {
                uint32_t sw = SW64((uint32_t)((wm + mt * 16 + lr) * 64 + ks * 32 + lk));
                uint32_t a_h[4], a_l[4];
                ldsm4(a_h[0], a_h[1], a_h[2], a_h[3], sb + sw);
                ldsm4(a_l[0], a_l[1], a_l[2], a_l[3], sb + 8192 + sw);
#pragma unroll
                for (int nt = 0; nt < 4; ++nt) {
                    mma16816(acc[mt][nt], a_h, bh0[nt], bh1[nt]);
                    mma16816(acc[mt][nt], a_h, bl0[nt], bl1[nt]);
                    mma16816(acc[mt][nt], a_l, bh0[nt], bh1[nt]);
                }
            }
        }
        __syncthreads();
    }

    int rbase = lane >> 2, cpair = (lane & 3) * 2;
#pragma unroll
    for (int mt = 0; mt < 4; ++mt)
#pragma unroll
        for (int e2 = 0; e2 < 2; ++e2) {
            int m = m0 + wm + mt * 16 + rbase + e2 * 8;
#pragma unroll
            for (int nt = 0; nt < 4; ++nt) {
                size_t idx = (size_t)m * H_DIM + n0 + wn + nt * 8 + cpair;
                *(float2*)&g_u[idx] = make_float2(acc[mt][nt][e2 * 2 + 0],
                                                  acc[mt][nt][e2 * 2 + 1]);
            }
        }
}

// ---------------- weights + iteration 0 ----------------
__global__ void k_weights(const float* __restrict__ alpha, const float* __restrict__ beta, int T) {
    int i = threadIdx.x;
    if (i >= T) return;
    float m = -1e30f;
    for (int k = 0; k < NOPS; ++k) m = fmaxf(m, alpha[i * NOPS + k]);
    float e[NOPS], s = 0.f;
    for (int k = 0; k < NOPS; ++k) { e[k] = expf(alpha[i * NOPS + k] - m); s += e[k]; }
    float invs = 1.f / s;
    for (int k = 0; k < NOPS; ++k) g_w[i * 24 + k] = e[k] * invs;
    float b0 = beta[i * 2], b1 = beta[i * 2 + 1];
    float mb = fmaxf(b0, b1);
    float e0 = expf(b0 - mb), e1 = expf(b1 - mb);
    float ib = 1.f / (e0 + e1);
    g_w[i * 24 + 20] = e0 * ib;
    g_w[i * 24 + 21] = e1 * ib;
}
__global__ void k_iter0(float* outF) {
    __shared__ float smw[24];
    int t = threadIdx.x;
    if (t < 22) smw[t] = g_w[t];
    __syncthreads();
    float invL = g_scal[3], lam = g_scal[4];
    float bw1 = smw[21];
    float mom1 = 0.25f;
    float ca = 1.f + mom1 * (1.f - bw1);
    size_t idx = ((size_t)blockIdx.x * 256 + t) * 4;
    float4 uu = *(const float4*)&g_u[idx];
    float zo[4];
    zo[0] = act_mix(uu.x * invL, smw, lam);
    zo[1] = act_mix(uu.y * invL, smw, lam);
    zo[2] = act_mix(uu.z * invL, smw, lam);
    zo[3] = act_mix(uu.w * invL, smw, lam);
    if (outF) {
        *(float4*)&outF[idx] = make_float4(zo[0], zo[1], zo[2], zo[3]);
    } else {
        *(float4*)&g_z[idx] = make_float4(zo[0], zo[1], zo[2], zo[3]);
#pragma unroll
        for (int j = 0; j < 4; ++j) {
            float za = ca * zo[j];
            __nv_bfloat16 h = __float2bfloat16(za);
            g_ah[0][idx + j] = h;
            g_al[0][idx + j] = __float2bfloat16(za - __bfloat162float(h));
        }
    }
}

// ---------------- iteration: split-3 mma + fused epilogue, 2-stage, 1 barrier/chunk ----
__global__ __launch_bounds__(256, 2) void k_mma_iter(int inSel, int outSel, float* outF,
                                                     int iter, float mom_next, int is_last) {
    extern __shared__ char dsm[];
    __shared__ float smw[24];

    const __nv_bfloat16* __restrict__ ah = g_ah[inSel];
    const __nv_bfloat16* __restrict__ al = g_al[inSel];
    __nv_bfloat16* __restrict__ aho = g_ah[outSel];
    __nv_bfloat16* __restrict__ alo = g_al[outSel];

    int tid = threadIdx.x, wid = tid >> 5, lane = tid & 31;
    int m0 = blockIdx.y * 128, n0 = blockIdx.x * 128;
    int wm = (wid >> 2) * 64, wn = (wid & 3) * 32;

    char* tp = (char*)(((uintptr_t)dsm + 1023) & ~(uintptr_t)1023);
    uint32_t base = smem_u32(tp);
    if (tid < 22) smw[tid] = g_w[iter * 24 + tid];

    const uint4* pAH = (const uint4*)ah;
    const uint4* pAL = (const uint4*)al;
    const uint4* pBH = (const uint4*)g_Chi;
    const uint4* pBL = (const uint4*)g_Clo;

    float acc[4][4][4];
#pragma unroll
    for (int a = 0; a < 4; ++a)
#pragma unroll
        for (int b = 0; b < 4; ++b)
#pragma unroll
            for (int e = 0; e < 4; ++e) acc[a][b][e] = 0.f;

    int lrow[2], lg[2];
    uint32_t lsw[2];
#pragma unroll
    for (int j = 0; j < 2; ++j) {
        int s = tid + j * 256;
        lrow[j] = s >> 2; lg[j] = s & 3;
        lsw[j] = SW64((uint32_t)(lrow[j] * 64 + lg[j] * 16));
    }
    int lr = lane & 15, lk = (lane >> 4) * 16;

    // prologue: chunk 0 into stage 0
#pragma unroll
    for (int j = 0; j < 2; ++j) {
        size_t gA = (size_t)(m0 + lrow[j]) * (H_DIM / 8) + lg[j];
        size_t gB = (size_t)(n0 + lrow[j]) * (H_DIM / 8) + lg[j];
        CP_A16(base + lsw[j],          (const void*)(pAH + gA));
        CP_A16(base + 8192  + lsw[j],  (const void*)(pAL + gA));
        CP_A16(base + 16384 + lsw[j],  (const void*)(pBH + gB));
        CP_A16(base + 24576 + lsw[j],  (const void*)(pBL + gB));
    }
    CP_COMMIT();

    // single barrier per chunk: wait(chunk c) -> barrier (also retires reads of
    // buf (c-1)&1 by all warps) -> issue chunk c+1 into (c+1)&1 -> compute c.
    for (int c = 0; c < NCH2; ++c) {
        CP_WAIT(0);
        __syncthreads();
        if (c + 1 < NCH2) {
            uint32_t nb = base + (uint32_t)(((c + 1) & 1) * 32768);
            int k4 = (c + 1) * 4;
#pragma unroll
            for (int j = 0; j < 2; ++j) {
                size_t gA = (size_t)(m0 + lrow[j]) * (H_DIM / 8) + k4 + lg[j];
                size_t gB = (size_t)(n0 + lrow[j]) * (H_DIM / 8) + k4 + lg[j];
                CP_A16(nb + lsw[j],          (const void*)(pAH + gA));
                CP_A16(nb + 8192  + lsw[j],  (const void*)(pAL + gA));
                CP_A16(nb + 16384 + lsw[j],  (const void*)(pBH + gB));
                CP_A16(nb + 24576 + lsw[j],  (const void*)(pBL + gB));
            }
            CP_COMMIT();
        }
        uint32_t sb = base + (uint32_t)((c & 1) * 32768);
#pragma unroll
        for (int ks = 0; ks < 2; ++ks) {
            uint32_t bh0[4], bh1[4], bl0[4], bl1[4];
#pragma unroll
            for (int np = 0; np < 2; ++np) {
                uint32_t sw = SW64((uint32_t)((wn + np * 16 + lr) * 64 + ks * 32 + lk));
                uint32_t r0, r1, r2, r3;
                ldsm4(r0, r1, r2, r3, sb + 16384 + sw);
                bh0[np * 2] = r0; bh0[np * 2 + 1] = r1; bh1[np * 2] = r2; bh1[np * 2 + 1] = r3;
                ldsm4(r0, r1, r2, r3, sb + 24576 + sw);
                bl0[np * 2] = r0; bl0[np * 2 + 1] = r1; bl1[np * 2] = r2; bl1[np * 2 + 1] = r3;
            }
#pragma unroll
            for (int mt = 0; mt < 4; ++mt) {
                uint32_t sw = SW64((uint32_t)((wm + mt * 16 + lr) * 64 + ks * 32 + lk));
                uint32_t a_h[4], a_l[4];
                ldsm4(a_h[0], a_h[1], a_h[2], a_h[3], sb + sw);
                ldsm4(a_l[0], a_l[1], a_l[2], a_l[3], sb + 8192 + sw);
#pragma unroll
                for (int nt = 0; nt < 4; ++nt) {
                    mma16816(acc[mt][nt], a_h, bh0[nt], bh1[nt]);
                    mma16816(acc[mt][nt], a_h, bl0[nt], bl1[nt]);
                    mma16816(acc[mt][nt], a_l, bh0[nt], bh1[nt]);
                }
            }
        }
    }

    // ---- fused epilogue straight from register accumulators ----
    float invL = g_scal[3], lam = g_scal[4];
    float bw0 = smw[20], bw1 = smw[21];
    float ca = 1.f + mom_next * (1.f - bw1);
    float cb = mom_next * bw0;
    int rbase = lane >> 2, cpair = (lane & 3) * 2;
#pragma unroll
    for (int mt = 0; mt < 4; ++mt) {
#pragma unroll
        for (int e2 = 0; e2 < 2; ++e2) {
            int m = m0 + wm + mt * 16 + rbase + e2 * 8;
            size_t rowoff = (size_t)m * H_DIM;
#pragma unroll
            for (int nt = 0; nt < 4; ++nt) {
                size_t idx = rowoff + n0 + wn + nt * 8 + cpair;
                float d0 = acc[mt][nt][e2 * 2 + 0];
                float d1 = acc[mt][nt][e2 * 2 + 1];
                __nv_bfloat162 h2 = *(const __nv_bfloat162*)&ah[idx];
                __nv_bfloat162 l2 = *(const __nv_bfloat162*)&al[idx];
                float2 u2 = *(const float2*)&g_u[idx];
                float za0 = __bfloat162float(h2.x) + __bfloat162float(l2.x);
                float za1 = __bfloat162float(h2.y) + __bfloat162float(l2.y);
                float zg0 = za0 - (d0 - u2.x) * invL;
                float zg1 = za1 - (d1 - u2.y) * invL;
                float zop0 = act_mix(zg0, smw, lam);
                float zop1 = act_mix(zg1, smw, lam);
                if (is_last) {
                    *(float2*)&outF[idx] = make_float2(zop0, zop1);
                } else {
                    float2 z2 = *(const float2*)&g_z[idx];
                    *(float2*)&g_z[idx] = make_float2(zop0, zop1);
                    float zan0 = ca * zop0 - cb * z2.x;
                    float zan1 = ca * zop1 - cb * z2.y;
                    __nv_bfloat162 ho, lo2;
                    ho.x = __float2bfloat16(zan0);
                    ho.y = __float2bfloat16(zan1);
                    lo2.x = __float2bfloat16(zan0 - __bfloat162float(ho.x));
                    lo2.y = __float2bfloat16(zan1 - __bfloat162float(ho.y));
                    *(__nv_bfloat162*)&aho[idx] = ho;
                    *(__nv_bfloat162*)&alo[idx] = lo2;
                }
            }
        }
    }
}

// ---------------- host orchestration (graph-capturable: kernel launches only) ----------------
extern "C" void kernel_launch(void* const* d_in, const int* in_sizes, int n_in,
                              void* d_out, int out_size) {
    const float* x     = (const float*)d_in[0];
    const float* W     = (const float*)d_in[1];
    const float* alpha = (const float*)d_in[2];
    const float* lbeta = (const float*)d_in[3];
    float* out = (float*)d_out;
    int T = in_sizes[2] / NOPS;
    if (T < 1) T = 1;
    if (T > 16) T = 16;

    const int DSM = 2 * 32768 + 1024;
    cudaFuncSetAttribute(k_mma_iter, cudaFuncAttributeMaxDynamicSharedMemorySize, DSM);
    cudaFuncSetAttribute(k_C_mma,   cudaFuncAttributeMaxDynamicSharedMemorySize, DSM);
    cudaFuncSetAttribute(k_u_mma,   cudaFuncAttributeMaxDynamicSharedMemorySize, DSM);

    dim3 thr(256);

    k_wwT64<<<dim3(8, 8), thr>>>(W);
    k_chain<<<dim3(8, 8), thr>>>();

    k_prepWt<<<dim3(H_DIM / 32, N_DIM / 32), thr>>>(W);
    k_splitX<<<(B_DIM * N_DIM) / (256 * 4), thr>>>(x);
    k_C_mma<<<dim3(8, 8), thr, DSM>>>();
    k_u_mma<<<dim3(8, 32), thr, DSM>>>();
    k_weights<<<1, 32>>>(alpha, lbeta, T);

    k_iter0<<<(B_DIM * H_DIM) / (256 * 4), thr>>>((T == 1) ? out : nullptr);

    for (int i = 1; i < T; ++i) {
        float mom_next = (float)((double)(i + 1) / (double)(i + 4));
        int inSel  = (i + 1) & 1;
        int outSel = i & 1;
        int last = (i == T - 1);
        k_mma_iter<<<dim3(8, 32), thr, DSM>>>(inSel, outSel, last ? out : nullptr,
                                              i, mom_next, last);
    }
}